// round 1
// baseline (speedup 1.0000x reference)
#include <cuda_runtime.h>
#include <math.h>

#define NN  20000
#define EE  320000
#define DD  128
#define DEH 64

// ---------------- scratch (device globals; no allocation allowed) ----------------
__device__ float g_h[NN * DD];        // node_fc output h            (10.24 MB)
__device__ float g_acc[NN * 512];     // per-node [P | Q0 | Q1 | Q2] (40.96 MB)
__device__ float g_za[NN];            // sum exp(a) per dst
__device__ float g_zg[NN * 3];        // sum exp(g_m) per dst
__device__ float g_C[4 * DD * DD];    // folded matrices C0..C3     (256 KB)

__device__ __forceinline__ float sigmoidf_(float x) { return 1.f / (1.f + __expf(-x)); }

// ---------------- kernel A: h = nf @ node_fc_W + b ----------------
// warp per node, weights in smem, float4 weight reads
__global__ void __launch_bounds__(256) k_node_fc(const float* __restrict__ nf,
                                                 const float* __restrict__ W,
                                                 const float* __restrict__ b)
{
    extern __shared__ float sm[];
    float* Wsm = sm;                 // 16384
    float* bsm = sm + 16384;         // 128
    float* buf = sm + 16384 + 128;   // 8 * 128
    int tid = threadIdx.x;
    for (int i = tid; i < DD * DD; i += blockDim.x) Wsm[i] = W[i];
    if (tid < DD) bsm[tid] = b[tid];
    __syncthreads();

    int warp = tid >> 5, lane = tid & 31;
    int n = blockIdx.x * 8 + warp;
    if (n >= NN) return;
    float* wb = buf + warp * DD;
    float4 x = *(const float4*)&nf[n * DD + lane * 4];
    *(float4*)&wb[lane * 4] = x;
    __syncwarp();
    float4 acc = *(float4*)&bsm[lane * 4];
    const float4* W4 = (const float4*)Wsm;
    #pragma unroll 8
    for (int k = 0; k < DD; k++) {
        float v = wb[k];
        float4 w = W4[k * 32 + lane];
        acc.x += v * w.x; acc.y += v * w.y; acc.z += v * w.z; acc.w += v * w.w;
    }
    *(float4*)&g_h[n * DD + lane * 4] = acc;
}

// ---------------- kernel P: fold C0 = Wsum@U_top, Cm = W_m@U_bot ----------------
__global__ void k_combine(const float* __restrict__ natt,
                          const float* __restrict__ relW,
                          const float* __restrict__ outW)
{
    __shared__ float row[DD];
    int i = blockIdx.x >> 7;          // 0..3 (mat)
    int d = blockIdx.x & 127;         // row
    int c = threadIdx.x;              // col
    if (i == 0)
        row[c] = natt[d * DD + c] + natt[DD * DD + d * DD + c] + natt[2 * DD * DD + d * DD + c];
    else
        row[c] = relW[(i - 1) * DD * DD + d * DD + c];
    __syncthreads();
    const float* U = (i == 0) ? outW : outW + DD * DD;   // out_fc_W top / bottom half
    float acc = 0.f;
    #pragma unroll 8
    for (int f = 0; f < DD; f++) acc += row[f] * U[f * DD + c];
    g_C[i * DD * DD + d * DD + c] = acc;
}

// ---------------- kernel B: per-edge pass (warp handles 2 edges) ----------------
// computes he = ef@edge_fc+b, g_m = sigmoid(relu(he@W1_m+b1)·W2_m + b2),
// a = <h[src],h[dst]>; scatters exp-weighted h[src] into g_acc and normalizers.
__global__ void __launch_bounds__(512, 1) k_edge(const float* __restrict__ ef,
                                                 const int*   __restrict__ src,
                                                 const int*   __restrict__ dst,
                                                 const float* __restrict__ efcW,
                                                 const float* __restrict__ efcb,
                                                 const float* __restrict__ W1,
                                                 const float* __restrict__ b1,
                                                 const float* __restrict__ W2,
                                                 const float* __restrict__ b2)
{
    extern __shared__ float sm[];
    float* Wfc = sm;                   // 4096
    float* W1s = sm + 4096;            // 24576
    float* bfc = W1s + 24576;          // 64
    float* b1s = bfc + 64;             // 384
    float* W2s = b1s + 384;            // 384
    float* b2s = W2s + 384;            // 4 (pad)
    float* buf = b2s + 4;              // 16 warps * 128
    int tid = threadIdx.x;
    for (int i = tid; i < 4096;  i += 512) Wfc[i] = efcW[i];
    for (int i = tid; i < 24576; i += 512) W1s[i] = W1[i];
    if (tid < 64)  bfc[tid] = efcb[tid];
    if (tid < 384) { b1s[tid] = b1[tid]; W2s[tid] = W2[tid]; }
    if (tid < 3)   b2s[tid] = b2[tid];
    __syncthreads();

    int warp = tid >> 5, lane = tid & 31;
    float* wb = buf + warp * 128;
    int wg = blockIdx.x * 16 + warp;
    const int npairs = EE / 2;
    const int stride = gridDim.x * 16;

    for (int p = wg; p < npairs; p += stride) {
        int e0 = 2 * p, e1 = e0 + 1;
        int s0 = src[e0], s1 = src[e1];
        int d0 = dst[e0], d1 = dst[e1];

        // prefetch h gathers early (hide long-scoreboard behind the GEMV work)
        float4 hs0 = *(const float4*)&g_h[s0 * DD + lane * 4];
        float4 hd0 = *(const float4*)&g_h[d0 * DD + lane * 4];
        float4 hs1 = *(const float4*)&g_h[s1 * DD + lane * 4];
        float4 hd1 = *(const float4*)&g_h[d1 * DD + lane * 4];

        __syncwarp();
        wb[lane]      = ef[e0 * DEH + lane];
        wb[32 + lane] = ef[e0 * DEH + 32 + lane];
        wb[64 + lane] = ef[e1 * DEH + lane];
        wb[96 + lane] = ef[e1 * DEH + 32 + lane];
        __syncwarp();

        // he for both edges; lane owns outputs {lane, lane+32}
        float h00 = bfc[lane], h01 = bfc[32 + lane];
        float h10 = h00,       h11 = h01;
        #pragma unroll 4
        for (int k = 0; k < DEH; k++) {
            float w0 = Wfc[k * DEH + lane], w1 = Wfc[k * DEH + 32 + lane];
            float v0 = wb[k], v1 = wb[64 + k];
            h00 += v0 * w0; h01 += v0 * w1;
            h10 += v1 * w0; h11 += v1 * w1;
        }
        __syncwarp();
        wb[lane] = h00; wb[32 + lane] = h01;
        wb[64 + lane] = h10; wb[96 + lane] = h11;
        __syncwarp();

        // t = relu(he@W1_m + b1), g = sigmoid(t·W2_m + b2); both edges at once
        float eg0[3], eg1[3];
        #pragma unroll
        for (int m = 0; m < 3; m++) {
            float4 bb = *(float4*)&b1s[m * DD + lane * 4];
            float4 a0 = bb, a1 = bb;
            const float4* Wm = (const float4*)(W1s + m * 8192);
            #pragma unroll 4
            for (int k = 0; k < DEH; k++) {
                float4 w = Wm[k * 32 + lane];
                float v0 = wb[k], v1 = wb[64 + k];
                a0.x += v0 * w.x; a0.y += v0 * w.y; a0.z += v0 * w.z; a0.w += v0 * w.w;
                a1.x += v1 * w.x; a1.y += v1 * w.y; a1.z += v1 * w.z; a1.w += v1 * w.w;
            }
            a0.x = fmaxf(a0.x, 0.f); a0.y = fmaxf(a0.y, 0.f);
            a0.z = fmaxf(a0.z, 0.f); a0.w = fmaxf(a0.w, 0.f);
            a1.x = fmaxf(a1.x, 0.f); a1.y = fmaxf(a1.y, 0.f);
            a1.z = fmaxf(a1.z, 0.f); a1.w = fmaxf(a1.w, 0.f);
            float4 w2 = *(float4*)&W2s[m * DD + lane * 4];
            float p0 = a0.x * w2.x + a0.y * w2.y + a0.z * w2.z + a0.w * w2.w;
            float p1 = a1.x * w2.x + a1.y * w2.y + a1.z * w2.z + a1.w * w2.w;
            #pragma unroll
            for (int off = 16; off; off >>= 1) {
                p0 += __shfl_xor_sync(0xffffffffu, p0, off);
                p1 += __shfl_xor_sync(0xffffffffu, p1, off);
            }
            eg0[m] = __expf(sigmoidf_(p0 + b2s[m]));
            eg1[m] = __expf(sigmoidf_(p1 + b2s[m]));
        }

        // a = <hs,hd>
        float pa0 = hs0.x * hd0.x + hs0.y * hd0.y + hs0.z * hd0.z + hs0.w * hd0.w;
        float pa1 = hs1.x * hd1.x + hs1.y * hd1.y + hs1.z * hd1.z + hs1.w * hd1.w;
        #pragma unroll
        for (int off = 16; off; off >>= 1) {
            pa0 += __shfl_xor_sync(0xffffffffu, pa0, off);
            pa1 += __shfl_xor_sync(0xffffffffu, pa1, off);
        }
        float ea0 = __expf(pa0), ea1 = __expf(pa1);

        // normalizer atomics
        if (lane == 0) {
            atomicAdd(&g_za[d0], ea0);
            atomicAdd(&g_zg[d0 * 3 + 0], eg0[0]);
            atomicAdd(&g_zg[d0 * 3 + 1], eg0[1]);
            atomicAdd(&g_zg[d0 * 3 + 2], eg0[2]);
        } else if (lane == 1) {
            atomicAdd(&g_za[d1], ea1);
            atomicAdd(&g_zg[d1 * 3 + 0], eg1[0]);
            atomicAdd(&g_zg[d1 * 3 + 1], eg1[1]);
            atomicAdd(&g_zg[d1 * 3 + 2], eg1[2]);
        }

        // scatter weighted h[src] (vector fp32 reductions, cc>=9.0)
        float4* A0 = (float4*)(g_acc + (size_t)d0 * 512) + lane;
        atomicAdd(A0,      make_float4(ea0 * hs0.x, ea0 * hs0.y, ea0 * hs0.z, ea0 * hs0.w));
        atomicAdd(A0 + 32, make_float4(eg0[0] * hs0.x, eg0[0] * hs0.y, eg0[0] * hs0.z, eg0[0] * hs0.w));
        atomicAdd(A0 + 64, make_float4(eg0[1] * hs0.x, eg0[1] * hs0.y, eg0[1] * hs0.z, eg0[1] * hs0.w));
        atomicAdd(A0 + 96, make_float4(eg0[2] * hs0.x, eg0[2] * hs0.y, eg0[2] * hs0.z, eg0[2] * hs0.w));
        float4* A1 = (float4*)(g_acc + (size_t)d1 * 512) + lane;
        atomicAdd(A1,      make_float4(ea1 * hs1.x, ea1 * hs1.y, ea1 * hs1.z, ea1 * hs1.w));
        atomicAdd(A1 + 32, make_float4(eg1[0] * hs1.x, eg1[0] * hs1.y, eg1[0] * hs1.z, eg1[0] * hs1.w));
        atomicAdd(A1 + 64, make_float4(eg1[1] * hs1.x, eg1[1] * hs1.y, eg1[1] * hs1.z, eg1[1] * hs1.w));
        atomicAdd(A1 + 96, make_float4(eg1[2] * hs1.x, eg1[2] * hs1.y, eg1[2] * hs1.z, eg1[2] * hs1.w));
    }
}

// ---------------- kernel D: finalize per node ----------------
// pre = [P/(K za) | Q_m/(M zg_m)] @ [C0;C1;C2;C3] + out_fc_b ; relu ; deg-mask ; gate mix
__global__ void __launch_bounds__(256, 1) k_final(const float* __restrict__ nf,
                                                  const float* __restrict__ outb,
                                                  const float* __restrict__ gW,
                                                  const float* __restrict__ gb,
                                                  float* __restrict__ out)
{
    extern __shared__ float sm[];
    float* Wsm = sm;            // 32768 (two 128x128 mats at a time)
    float* xbb = sm + 32768;    // 8 warps * 4 nodes * 256
    int tid = threadIdx.x;
    int warp = tid >> 5, lane = tid & 31;
    float* xb = xbb + warp * 1024;

    for (int i = tid; i < 32768; i += 256) Wsm[i] = g_C[i];
    __syncthreads();

    int nbase = blockIdx.x * 32 + warp * 4;
    float4 acc[4];
    float s0[4], s1[4], s2[4], s3[4];
    bool ok[4];
    #pragma unroll
    for (int t = 0; t < 4; t++) {
        int n = nbase + t;
        float za = g_za[n];
        ok[t] = (za > 0.f);
        s0[t] = ok[t] ? 1.f / (3.f * za) : 0.f;
        s1[t] = ok[t] ? 1.f / (3.f * g_zg[n * 3 + 0]) : 0.f;
        s2[t] = ok[t] ? 1.f / (3.f * g_zg[n * 3 + 1]) : 0.f;
        s3[t] = ok[t] ? 1.f / (3.f * g_zg[n * 3 + 2]) : 0.f;
        acc[t] = make_float4(0.f, 0.f, 0.f, 0.f);
    }

    // phase 1: segments 0 (P) and 1 (Q0) against C0,C1
    #pragma unroll
    for (int t = 0; t < 4; t++) {
        int n = nbase + t;
        float4 v0 = *(const float4*)&g_acc[(size_t)n * 512 + lane * 4];
        float4 v1 = *(const float4*)&g_acc[(size_t)n * 512 + 128 + lane * 4];
        *(float4*)&xb[t * 256 + lane * 4]       = make_float4(v0.x * s0[t], v0.y * s0[t], v0.z * s0[t], v0.w * s0[t]);
        *(float4*)&xb[t * 256 + 128 + lane * 4] = make_float4(v1.x * s1[t], v1.y * s1[t], v1.z * s1[t], v1.w * s1[t]);
    }
    __syncwarp();
    {
        const float4* W4 = (const float4*)Wsm;
        #pragma unroll 4
        for (int k = 0; k < 256; k++) {
            float4 w = W4[k * 32 + lane];
            #pragma unroll
            for (int t = 0; t < 4; t++) {
                float v = xb[t * 256 + k];
                acc[t].x += v * w.x; acc[t].y += v * w.y;
                acc[t].z += v * w.z; acc[t].w += v * w.w;
            }
        }
    }
    __syncthreads();
    for (int i = tid; i < 32768; i += 256) Wsm[i] = g_C[32768 + i];
    __syncthreads();

    // phase 2: segments 2 (Q1) and 3 (Q2) against C2,C3
    #pragma unroll
    for (int t = 0; t < 4; t++) {
        int n = nbase + t;
        float4 v2 = *(const float4*)&g_acc[(size_t)n * 512 + 256 + lane * 4];
        float4 v3 = *(const float4*)&g_acc[(size_t)n * 512 + 384 + lane * 4];
        *(float4*)&xb[t * 256 + lane * 4]       = make_float4(v2.x * s2[t], v2.y * s2[t], v2.z * s2[t], v2.w * s2[t]);
        *(float4*)&xb[t * 256 + 128 + lane * 4] = make_float4(v3.x * s3[t], v3.y * s3[t], v3.z * s3[t], v3.w * s3[t]);
    }
    __syncwarp();
    {
        const float4* W4 = (const float4*)Wsm;
        #pragma unroll 4
        for (int k = 0; k < 256; k++) {
            float4 w = W4[k * 32 + lane];
            #pragma unroll
            for (int t = 0; t < 4; t++) {
                float v = xb[t * 256 + k];
                acc[t].x += v * w.x; acc[t].y += v * w.y;
                acc[t].z += v * w.z; acc[t].w += v * w.w;
            }
        }
    }

    // finalize
    float4 b4  = *(const float4*)&outb[lane * 4];
    float4 gw4 = *(const float4*)&gW[lane * 4];
    float gb0 = __ldg(gb);
    #pragma unroll
    for (int t = 0; t < 4; t++) {
        int n = nbase + t;
        float4 pre = make_float4(fmaxf(acc[t].x + b4.x, 0.f), fmaxf(acc[t].y + b4.y, 0.f),
                                 fmaxf(acc[t].z + b4.z, 0.f), fmaxf(acc[t].w + b4.w, 0.f));
        float4 hv  = *(const float4*)&g_h[n * DD + lane * 4];
        float4 ho  = ok[t] ? pre : hv;
        float4 nfv = *(const float4*)&nf[n * DD + lane * 4];
        float gp = nfv.x * gw4.x + nfv.y * gw4.y + nfv.z * gw4.z + nfv.w * gw4.w;
        #pragma unroll
        for (int off = 16; off; off >>= 1) gp += __shfl_xor_sync(0xffffffffu, gp, off);
        float gate = sigmoidf_(gp + gb0);
        float4 o = make_float4(gate * ho.x + (1.f - gate) * nfv.x,
                               gate * ho.y + (1.f - gate) * nfv.y,
                               gate * ho.z + (1.f - gate) * nfv.z,
                               gate * ho.w + (1.f - gate) * nfv.w);
        *(float4*)&out[n * DD + lane * 4] = o;
    }
}

// ---------------- launcher ----------------
extern "C" void kernel_launch(void* const* d_in, const int* in_sizes, int n_in,
                              void* d_out, int out_size)
{
    const float* nf   = (const float*)d_in[0];
    const float* ef   = (const float*)d_in[1];
    const int*   src  = (const int*)  d_in[2];
    const int*   dst  = (const int*)  d_in[3];
    const float* natt = (const float*)d_in[4];
    const float* relW = (const float*)d_in[5];
    const float* W1   = (const float*)d_in[6];
    const float* b1   = (const float*)d_in[7];
    const float* W2   = (const float*)d_in[8];
    const float* b2   = (const float*)d_in[9];
    const float* nfcW = (const float*)d_in[10];
    const float* nfcb = (const float*)d_in[11];
    const float* efcW = (const float*)d_in[12];
    const float* efcb = (const float*)d_in[13];
    const float* outb = (const float*)d_in[15];
    const float* gW   = (const float*)d_in[16];
    const float* gb   = (const float*)d_in[17];
    float* out = (float*)d_out;

    void *pAcc, *pZa, *pZg;
    cudaGetSymbolAddress(&pAcc, g_acc);
    cudaGetSymbolAddress(&pZa,  g_za);
    cudaGetSymbolAddress(&pZg,  g_zg);
    cudaMemsetAsync(pAcc, 0, (size_t)NN * 512 * sizeof(float));
    cudaMemsetAsync(pZa,  0, (size_t)NN * sizeof(float));
    cudaMemsetAsync(pZg,  0, (size_t)NN * 3 * sizeof(float));

    const int SMEM_A = (16384 + 128 + 8 * 128) * 4;
    const int SMEM_B = (4096 + 24576 + 64 + 384 + 384 + 4 + 16 * 128) * 4;
    const int SMEM_D = (32768 + 8 * 1024) * 4;
    cudaFuncSetAttribute(k_node_fc, cudaFuncAttributeMaxDynamicSharedMemorySize, SMEM_A);
    cudaFuncSetAttribute(k_edge,    cudaFuncAttributeMaxDynamicSharedMemorySize, SMEM_B);
    cudaFuncSetAttribute(k_final,   cudaFuncAttributeMaxDynamicSharedMemorySize, SMEM_D);

    k_node_fc<<<(NN + 7) / 8, 256, SMEM_A>>>(nf, nfcW, nfcb);
    k_combine<<<512, 128>>>(natt, relW, (const float*)d_in[14]);
    k_edge<<<148, 512, SMEM_B>>>(ef, src, dst, efcW, efcb, W1, b1, W2, b2);
    k_final<<<625, 256, SMEM_D>>>(nf, outb, gW, gb, out);
}

// round 3
// speedup vs baseline: 2.1203x; 2.1203x over previous
#include <cuda_runtime.h>
#include <cuda_bf16.h>
#include <math.h>
#include <stdint.h>

#define NN  20000
#define EE  320000
#define DD  128
#define DEH 64
#define NTILES (EE / 128)   // 2500
#define GRID_MLP 148

// ---------------- scratch (device globals; no allocation allowed) ----------------
__device__ float g_h[NN * DD];                 // node_fc output h
__device__ float g_acc[NN * 512];              // per-node [P | Q0 | Q1 | Q2]
__device__ float g_za[NN];                     // sum exp(a) per dst
__device__ float g_zg[NN * 3];                 // sum exp(g_m) per dst
__device__ float g_C[4 * DD * DD];             // folded matrices C0..C3
__device__ float g_eg[3 * EE];                 // exp(sigmoid(g)) per edge, [m][E]
__device__ float g_B[384 * 64];                // folded MLP weights Gᵀ (tf32-rounded fp32)
__device__ float g_bb[384];                    // folded bias bb1

__device__ __forceinline__ float sigmoidf_(float x) { return 1.f / (1.f + __expf(-x)); }

__device__ __forceinline__ uint32_t smem_to_u32(const void* p) {
    uint32_t a;
    asm("{ .reg .u64 t; cvta.to.shared.u64 t, %1; cvt.u32.u64 %0, t; }" : "=r"(a) : "l"(p));
    return a;
}
__device__ __forceinline__ uint32_t tf32_rna(float x) {
    uint32_t r; asm("cvt.rna.tf32.f32 %0, %1;" : "=r"(r) : "f"(x)); return r;
}
__device__ __forceinline__ void mma_tf32(float& c0, float& c1, float& c2, float& c3,
                                         uint32_t a0, uint32_t a1, uint32_t a2, uint32_t a3,
                                         uint32_t b0, uint32_t b1) {
    asm volatile("mma.sync.aligned.m16n8k8.row.col.f32.tf32.tf32.f32 "
                 "{%0,%1,%2,%3}, {%4,%5,%6,%7}, {%8,%9}, {%0,%1,%2,%3};"
                 : "+f"(c0), "+f"(c1), "+f"(c2), "+f"(c3)
                 : "r"(a0), "r"(a1), "r"(a2), "r"(a3), "r"(b0), "r"(b1));
}
__device__ __forceinline__ void cp16(float* dst_smem, const float* src) {
    uint32_t d = smem_to_u32(dst_smem);
    asm volatile("cp.async.ca.shared.global [%0], [%1], 16;" :: "r"(d), "l"(src));
}
#define CP_COMMIT asm volatile("cp.async.commit_group;" ::: "memory")
#define CP_WAIT1  asm volatile("cp.async.wait_group 1;"  ::: "memory")

// ---------------- kernel A: h = nf @ node_fc_W + b ----------------
__global__ void __launch_bounds__(256) k_node_fc(const float* __restrict__ nf,
                                                 const float* __restrict__ W,
                                                 const float* __restrict__ b)
{
    extern __shared__ float sm[];
    float* Wsm = sm;                 // 16384
    float* bsm = sm + 16384;         // 128
    float* buf = sm + 16384 + 128;   // 8 * 128
    int tid = threadIdx.x;
    for (int i = tid; i < DD * DD; i += blockDim.x) Wsm[i] = W[i];
    if (tid < DD) bsm[tid] = b[tid];
    __syncthreads();

    int warp = tid >> 5, lane = tid & 31;
    int n = blockIdx.x * 8 + warp;
    if (n >= NN) return;
    float* wb = buf + warp * DD;
    float4 x = *(const float4*)&nf[n * DD + lane * 4];
    *(float4*)&wb[lane * 4] = x;
    __syncwarp();
    float4 acc = *(float4*)&bsm[lane * 4];
    const float4* W4 = (const float4*)Wsm;
    #pragma unroll 8
    for (int k = 0; k < DD; k++) {
        float v = wb[k];
        float4 w = W4[k * 32 + lane];
        acc.x += v * w.x; acc.y += v * w.y; acc.z += v * w.z; acc.w += v * w.w;
    }
    *(float4*)&g_h[n * DD + lane * 4] = acc;
}

// ---------------- kernel P1: fold C0 = Wsum@U_top, Cm = W_m@U_bot ----------------
__global__ void k_combine(const float* __restrict__ natt,
                          const float* __restrict__ relW,
                          const float* __restrict__ outW)
{
    __shared__ float row[DD];
    int i = blockIdx.x >> 7;
    int d = blockIdx.x & 127;
    int c = threadIdx.x;
    if (i == 0)
        row[c] = natt[d * DD + c] + natt[DD * DD + d * DD + c] + natt[2 * DD * DD + d * DD + c];
    else
        row[c] = relW[(i - 1) * DD * DD + d * DD + c];
    __syncthreads();
    const float* U = (i == 0) ? outW : outW + DD * DD;
    float acc = 0.f;
    #pragma unroll 8
    for (int f = 0; f < DD; f++) acc += row[f] * U[f * DD + c];
    g_C[i * DD * DD + d * DD + c] = acc;
}

// ---------------- kernel P2: fold G_m = efcW @ W1_m (tf32-rounded) + bias bb ----------------
// grid 384 (n = m*128+f), block 64 (k)
__global__ void k_prepF(const float* __restrict__ efcW,
                        const float* __restrict__ efcb,
                        const float* __restrict__ W1,
                        const float* __restrict__ b1)
{
    int n = blockIdx.x;
    int m = n >> 7, f = n & 127;
    int k = threadIdx.x;
    float acc = 0.f;
    #pragma unroll 4
    for (int fp = 0; fp < DEH; fp++)
        acc += efcW[k * DEH + fp] * W1[(m * DEH + fp) * DD + f];
    g_B[n * 64 + k] = __uint_as_float(tf32_rna(acc));
    if (k == 0) {
        float b = b1[n];   // b1 is [3,128] row-major == linear in n
        #pragma unroll 4
        for (int fp = 0; fp < DEH; fp++)
            b += efcb[fp] * W1[(m * DEH + fp) * DD + f];
        g_bb[n] = b;
    }
}

// ---------------- kernel B: tensor-core (mma.sync tf32) edge MLP -> g_eg ----------------
// smem floats: Bs [384][68] = 26112 | As 2x[128][68] = 17408 | epi 384 float2 = 768
#define B_STRIDE 68
#define A_BUF_F  (128 * B_STRIDE)          // 8704 floats
#define SMEM_MLP ((26112 + 2 * A_BUF_F + 768) * 4)

__global__ void __launch_bounds__(256, 1) k_mlp(const float* __restrict__ ef,
                                                const float* __restrict__ W2,
                                                const float* __restrict__ b2)
{
    extern __shared__ float sm[];
    float*  Bs  = sm;
    float*  As  = sm + 26112;
    float2* epi = (float2*)(sm + 26112 + 2 * A_BUF_F);

    int tid = threadIdx.x;
    int wid = tid >> 5, lane = tid & 31;
    int g = lane >> 2, tig = lane & 3;

    for (int i = tid; i < 384 * 64; i += 256) {
        int n = i >> 6, k = i & 63;
        Bs[n * B_STRIDE + k] = g_B[i];
    }
    for (int i = tid; i < 384; i += 256) epi[i] = make_float2(g_bb[i], __ldg(W2 + i));
    __syncthreads();

    float b2v[3] = {__ldg(b2), __ldg(b2 + 1), __ldg(b2 + 2)};

    // prologue: load first tile into buf 0
    int t0 = blockIdx.x;
    {
        const float* srcb = ef + (size_t)t0 * 8192;
        #pragma unroll
        for (int j = 0; j < 8; j++) {
            int c = j * 256 + tid;                 // 2048 chunks of 16B
            cp16(As + (c >> 4) * B_STRIDE + (c & 15) * 4, srcb + c * 4);
        }
    }
    CP_COMMIT;

    int buf = 0;
    for (int t = t0; t < NTILES; t += GRID_MLP) {
        int tn = t + GRID_MLP;
        if (tn < NTILES) {
            const float* srcb = ef + (size_t)tn * 8192;
            float* dstb = As + (buf ^ 1) * A_BUF_F;
            #pragma unroll
            for (int j = 0; j < 8; j++) {
                int c = j * 256 + tid;
                cp16(dstb + (c >> 4) * B_STRIDE + (c & 15) * 4, srcb + c * 4);
            }
        }
        CP_COMMIT;
        CP_WAIT1;              // current buf's group complete
        __syncthreads();

        // ---- compute from As[buf] ----
        const float* A = As + buf * A_BUF_F;
        int rowbase = wid * 16;
        const float* r0 = A + (rowbase + g) * B_STRIDE;
        const float* r1 = A + (rowbase + g + 8) * B_STRIDE;
        uint32_t a0[8], a1[8], a2[8], a3[8];
        #pragma unroll
        for (int kk = 0; kk < 8; kk++) {
            a0[kk] = tf32_rna(r0[kk * 8 + tig]);
            a2[kk] = tf32_rna(r0[kk * 8 + tig + 4]);
            a1[kk] = tf32_rna(r1[kk * 8 + tig]);
            a3[kk] = tf32_rna(r1[kk * 8 + tig + 4]);
        }

        float p00 = 0.f, p01 = 0.f, p02 = 0.f;
        float p10 = 0.f, p11 = 0.f, p12 = 0.f;
        #pragma unroll 4
        for (int nt = 0; nt < 48; nt++) {
            int n0 = nt * 8;
            float c0 = 0.f, c1 = 0.f, c2 = 0.f, c3 = 0.f;
            const float* bp = Bs + (n0 + g) * B_STRIDE;
            #pragma unroll
            for (int kk = 0; kk < 8; kk++) {
                uint32_t b0 = __float_as_uint(bp[kk * 8 + tig]);
                uint32_t b1 = __float_as_uint(bp[kk * 8 + tig + 4]);
                mma_tf32(c0, c1, c2, c3, a0[kk], a1[kk], a2[kk], a3[kk], b0, b1);
            }
            float2 e0 = epi[n0 + 2 * tig];
            float2 e1 = epi[n0 + 2 * tig + 1];
            float q0 = fmaxf(c0 + e0.x, 0.f) * e0.y + fmaxf(c1 + e1.x, 0.f) * e1.y;
            float q1 = fmaxf(c2 + e0.x, 0.f) * e0.y + fmaxf(c3 + e1.x, 0.f) * e1.y;
            if (nt < 16)      { p00 += q0; p10 += q1; }
            else if (nt < 32) { p01 += q0; p11 += q1; }
            else              { p02 += q0; p12 += q1; }
        }
        // reduce across the 4 lanes of each row-group
        #pragma unroll
        for (int off = 1; off <= 2; off <<= 1) {
            p00 += __shfl_xor_sync(0xffffffffu, p00, off);
            p01 += __shfl_xor_sync(0xffffffffu, p01, off);
            p02 += __shfl_xor_sync(0xffffffffu, p02, off);
            p10 += __shfl_xor_sync(0xffffffffu, p10, off);
            p11 += __shfl_xor_sync(0xffffffffu, p11, off);
            p12 += __shfl_xor_sync(0xffffffffu, p12, off);
        }
        if (tig == 0) {
            int e = t * 128 + rowbase + g;
            g_eg[e]            = __expf(sigmoidf_(p00 + b2v[0]));
            g_eg[EE + e]       = __expf(sigmoidf_(p01 + b2v[1]));
            g_eg[2 * EE + e]   = __expf(sigmoidf_(p02 + b2v[2]));
            g_eg[e + 8]          = __expf(sigmoidf_(p10 + b2v[0]));
            g_eg[EE + e + 8]     = __expf(sigmoidf_(p11 + b2v[1]));
            g_eg[2 * EE + e + 8] = __expf(sigmoidf_(p12 + b2v[2]));
        }
        __syncthreads();
        buf ^= 1;
    }
}

// ---------------- kernel C: scatter (warp per edge) ----------------
__global__ void __launch_bounds__(256) k_scatter(const int* __restrict__ src,
                                                 const int* __restrict__ dst)
{
    int gwarp = (blockIdx.x * blockDim.x + threadIdx.x) >> 5;
    int lane = threadIdx.x & 31;
    int nwarps = (gridDim.x * blockDim.x) >> 5;

    for (int e = gwarp; e < EE; e += nwarps) {
        int s = __ldg(src + e);
        int d = __ldg(dst + e);
        float4 hs = *(const float4*)&g_h[(size_t)s * DD + lane * 4];
        float4 hd = *(const float4*)&g_h[(size_t)d * DD + lane * 4];
        float pa = hs.x * hd.x + hs.y * hd.y + hs.z * hd.z + hs.w * hd.w;
        #pragma unroll
        for (int off = 16; off; off >>= 1) pa += __shfl_xor_sync(0xffffffffu, pa, off);
        float ea = __expf(pa);
        float e0 = g_eg[e], e1 = g_eg[EE + e], e2 = g_eg[2 * EE + e];

        if (lane == 0) {
            atomicAdd(&g_za[d], ea);
            atomicAdd(&g_zg[d * 3 + 0], e0);
            atomicAdd(&g_zg[d * 3 + 1], e1);
            atomicAdd(&g_zg[d * 3 + 2], e2);
        }
        float4* A = (float4*)(g_acc + (size_t)d * 512) + lane;
        atomicAdd(A,      make_float4(ea * hs.x, ea * hs.y, ea * hs.z, ea * hs.w));
        atomicAdd(A + 32, make_float4(e0 * hs.x, e0 * hs.y, e0 * hs.z, e0 * hs.w));
        atomicAdd(A + 64, make_float4(e1 * hs.x, e1 * hs.y, e1 * hs.z, e1 * hs.w));
        atomicAdd(A + 96, make_float4(e2 * hs.x, e2 * hs.y, e2 * hs.z, e2 * hs.w));
    }
}

// ---------------- kernel D: finalize per node ----------------
// 8 warps * 8 nodes, 4 phases of one 64KB C-matrix -> 96KB smem, 2 CTAs/SM
__global__ void __launch_bounds__(256, 2) k_final(const float* __restrict__ nf,
                                                  const float* __restrict__ outb,
                                                  const float* __restrict__ gW,
                                                  const float* __restrict__ gb,
                                                  float* __restrict__ out)
{
    extern __shared__ float sm[];
    float* Wsm = sm;            // 16384 floats
    float* xbb = sm + 16384;    // 8 warps * 8 nodes * 128 = 8192 floats
    int tid = threadIdx.x;
    int warp = tid >> 5, lane = tid & 31;
    float* xb = xbb + warp * 1024;
    int nbase = blockIdx.x * 64 + warp * 8;

    float4 acc[8];
    #pragma unroll
    for (int t = 0; t < 8; t++) acc[t] = make_float4(0.f, 0.f, 0.f, 0.f);

    for (int phph = 0; phph < 4; phph++) {
        __syncthreads();
        {
            const float4* src4 = (const float4*)(g_C + phph * 16384);
            float4* dst4 = (float4*)Wsm;
            #pragma unroll
            for (int i = 0; i < 16; i++) dst4[i * 256 + tid] = src4[i * 256 + tid];
        }
        #pragma unroll
        for (int t = 0; t < 8; t++) {
            int n = nbase + t;
            float4 v = make_float4(0.f, 0.f, 0.f, 0.f);
            float sc = 0.f;
            if (n < NN) {
                float za = g_za[n];
                if (za > 0.f) {
                    float den = (phph == 0) ? za : g_zg[n * 3 + (phph - 1)];
                    sc = 1.f / (3.f * den);
                    v = *(const float4*)&g_acc[(size_t)n * 512 + phph * 128 + lane * 4];
                }
            }
            *(float4*)&xb[t * 128 + lane * 4] = make_float4(v.x * sc, v.y * sc, v.z * sc, v.w * sc);
        }
        __syncthreads();
        const float4* W4 = (const float4*)Wsm;
        #pragma unroll 4
        for (int k = 0; k < 128; k++) {
            float4 w = W4[k * 32 + lane];
            #pragma unroll
            for (int t = 0; t < 8; t++) {
                float v = xb[t * 128 + k];
                acc[t].x += v * w.x; acc[t].y += v * w.y;
                acc[t].z += v * w.z; acc[t].w += v * w.w;
            }
        }
    }

    float4 b4  = *(const float4*)&outb[lane * 4];
    float4 gw4 = *(const float4*)&gW[lane * 4];
    float gb0 = __ldg(gb);
    #pragma unroll
    for (int t = 0; t < 8; t++) {
        int n = nbase + t;
        if (n >= NN) break;
        bool ok = (g_za[n] > 0.f);
        float4 pre = make_float4(fmaxf(acc[t].x + b4.x, 0.f), fmaxf(acc[t].y + b4.y, 0.f),
                                 fmaxf(acc[t].z + b4.z, 0.f), fmaxf(acc[t].w + b4.w, 0.f));
        float4 hv  = *(const float4*)&g_h[(size_t)n * DD + lane * 4];
        float4 ho  = ok ? pre : hv;
        float4 nfv = *(const float4*)&nf[(size_t)n * DD + lane * 4];
        float gp = nfv.x * gw4.x + nfv.y * gw4.y + nfv.z * gw4.z + nfv.w * gw4.w;
        #pragma unroll
        for (int off = 16; off; off >>= 1) gp += __shfl_xor_sync(0xffffffffu, gp, off);
        float gate = sigmoidf_(gp + gb0);
        float4 o = make_float4(gate * ho.x + (1.f - gate) * nfv.x,
                               gate * ho.y + (1.f - gate) * nfv.y,
                               gate * ho.z + (1.f - gate) * nfv.z,
                               gate * ho.w + (1.f - gate) * nfv.w);
        *(float4*)&out[(size_t)n * DD + lane * 4] = o;
    }
}

// ---------------- launcher ----------------
extern "C" void kernel_launch(void* const* d_in, const int* in_sizes, int n_in,
                              void* d_out, int out_size)
{
    const float* nf   = (const float*)d_in[0];
    const float* ef   = (const float*)d_in[1];
    const int*   src  = (const int*)  d_in[2];
    const int*   dst  = (const int*)  d_in[3];
    const float* natt = (const float*)d_in[4];
    const float* relW = (const float*)d_in[5];
    const float* W1   = (const float*)d_in[6];
    const float* b1   = (const float*)d_in[7];
    const float* W2   = (const float*)d_in[8];
    const float* b2   = (const float*)d_in[9];
    const float* nfcW = (const float*)d_in[10];
    const float* nfcb = (const float*)d_in[11];
    const float* efcW = (const float*)d_in[12];
    const float* efcb = (const float*)d_in[13];
    const float* outW = (const float*)d_in[14];
    const float* outb = (const float*)d_in[15];
    const float* gW   = (const float*)d_in[16];
    const float* gb   = (const float*)d_in[17];
    float* out = (float*)d_out;

    void *pAcc, *pZa, *pZg;
    cudaGetSymbolAddress(&pAcc, g_acc);
    cudaGetSymbolAddress(&pZa,  g_za);
    cudaGetSymbolAddress(&pZg,  g_zg);
    cudaMemsetAsync(pAcc, 0, (size_t)NN * 512 * sizeof(float));
    cudaMemsetAsync(pZa,  0, (size_t)NN * sizeof(float));
    cudaMemsetAsync(pZg,  0, (size_t)NN * 3 * sizeof(float));

    const int SMEM_A = (16384 + 128 + 8 * 128) * 4;
    const int SMEM_D = (16384 + 8192) * 4;
    cudaFuncSetAttribute(k_node_fc, cudaFuncAttributeMaxDynamicSharedMemorySize, SMEM_A);
    cudaFuncSetAttribute(k_mlp,     cudaFuncAttributeMaxDynamicSharedMemorySize, SMEM_MLP);
    cudaFuncSetAttribute(k_final,   cudaFuncAttributeMaxDynamicSharedMemorySize, SMEM_D);

    k_node_fc<<<(NN + 7) / 8, 256, SMEM_A>>>(nf, nfcW, nfcb);
    k_combine<<<512, 128>>>(natt, relW, outW);
    k_prepF<<<384, 64>>>(efcW, efcb, W1, b1);
    k_mlp<<<GRID_MLP, 256, SMEM_MLP>>>(ef, W2, b2);
    k_scatter<<<1184, 256>>>(src, dst);
    k_final<<<(NN + 63) / 64, 256, SMEM_D>>>(nf, outb, gW, gb, out);
}

// round 4
// speedup vs baseline: 2.3353x; 1.1014x over previous
#include <cuda_runtime.h>
#include <cuda_bf16.h>
#include <math.h>
#include <stdint.h>

#define NN  20000
#define EE  320000
#define DD  128
#define DEH 64
#define NTILES (EE / 128)   // 2500
#define GRID_MLP 148

// ---------------- scratch (device globals; no allocation allowed) ----------------
__device__ float g_h[NN * DD];                 // node_fc output h
__device__ float g_acc[NN * 512];              // per-node [P | Q0 | Q1 | Q2]
__device__ __align__(16) float g_z[NN * 4];    // [za, zg0, zg1, zg2] per dst
__device__ float g_C[4 * DD * DD];             // folded matrices C0..C3
__device__ float g_eg[3 * EE];                 // exp(sigmoid(g)) per edge, [m][E]
__device__ float g_B[384 * 64];                // folded MLP weights Gᵀ (tf32-rounded fp32)
__device__ float g_bb[384];                    // folded bias bb1

__device__ __forceinline__ float sigmoidf_(float x) { return 1.f / (1.f + __expf(-x)); }

__device__ __forceinline__ uint32_t smem_to_u32(const void* p) {
    uint32_t a;
    asm("{ .reg .u64 t; cvta.to.shared.u64 t, %1; cvt.u32.u64 %0, t; }" : "=r"(a) : "l"(p));
    return a;
}
__device__ __forceinline__ uint32_t tf32_rna(float x) {
    uint32_t r; asm("cvt.rna.tf32.f32 %0, %1;" : "=r"(r) : "f"(x)); return r;
}
__device__ __forceinline__ void mma_tf32(float& c0, float& c1, float& c2, float& c3,
                                         uint32_t a0, uint32_t a1, uint32_t a2, uint32_t a3,
                                         uint32_t b0, uint32_t b1) {
    asm volatile("mma.sync.aligned.m16n8k8.row.col.f32.tf32.tf32.f32 "
                 "{%0,%1,%2,%3}, {%4,%5,%6,%7}, {%8,%9}, {%0,%1,%2,%3};"
                 : "+f"(c0), "+f"(c1), "+f"(c2), "+f"(c3)
                 : "r"(a0), "r"(a1), "r"(a2), "r"(a3), "r"(b0), "r"(b1));
}
__device__ __forceinline__ void cp16(float* dst_smem, const float* src) {
    uint32_t d = smem_to_u32(dst_smem);
    asm volatile("cp.async.ca.shared.global [%0], [%1], 16;" :: "r"(d), "l"(src));
}
#define CP_COMMIT asm volatile("cp.async.commit_group;" ::: "memory")
#define CP_WAIT1  asm volatile("cp.async.wait_group 1;"  ::: "memory")

// ---------------- kernel A: h = nf @ node_fc_W + b ----------------
__global__ void __launch_bounds__(256) k_node_fc(const float* __restrict__ nf,
                                                 const float* __restrict__ W,
                                                 const float* __restrict__ b)
{
    extern __shared__ float sm[];
    float* Wsm = sm;                 // 16384
    float* bsm = sm + 16384;         // 128
    float* buf = sm + 16384 + 128;   // 8 * 128
    int tid = threadIdx.x;
    for (int i = tid; i < DD * DD; i += blockDim.x) Wsm[i] = W[i];
    if (tid < DD) bsm[tid] = b[tid];
    __syncthreads();

    int warp = tid >> 5, lane = tid & 31;
    int n = blockIdx.x * 8 + warp;
    if (n >= NN) return;
    float* wb = buf + warp * DD;
    float4 x = *(const float4*)&nf[n * DD + lane * 4];
    *(float4*)&wb[lane * 4] = x;
    __syncwarp();
    float4 acc = *(float4*)&bsm[lane * 4];
    const float4* W4 = (const float4*)Wsm;
    #pragma unroll 8
    for (int k = 0; k < DD; k++) {
        float v = wb[k];
        float4 w = W4[k * 32 + lane];
        acc.x += v * w.x; acc.y += v * w.y; acc.z += v * w.z; acc.w += v * w.w;
    }
    *(float4*)&g_h[n * DD + lane * 4] = acc;
}

// ---------------- kernel P1: fold C0 = Wsum@U_top, Cm = W_m@U_bot ----------------
__global__ void k_combine(const float* __restrict__ natt,
                          const float* __restrict__ relW,
                          const float* __restrict__ outW)
{
    __shared__ float row[DD];
    int i = blockIdx.x >> 7;
    int d = blockIdx.x & 127;
    int c = threadIdx.x;
    if (i == 0)
        row[c] = natt[d * DD + c] + natt[DD * DD + d * DD + c] + natt[2 * DD * DD + d * DD + c];
    else
        row[c] = relW[(i - 1) * DD * DD + d * DD + c];
    __syncthreads();
    const float* U = (i == 0) ? outW : outW + DD * DD;
    float acc = 0.f;
    #pragma unroll 8
    for (int f = 0; f < DD; f++) acc += row[f] * U[f * DD + c];
    g_C[i * DD * DD + d * DD + c] = acc;
}

// ---------------- kernel P2: fold G_m = efcW @ W1_m (tf32-rounded) + bias bb ----------------
__global__ void k_prepF(const float* __restrict__ efcW,
                        const float* __restrict__ efcb,
                        const float* __restrict__ W1,
                        const float* __restrict__ b1)
{
    int n = blockIdx.x;
    int m = n >> 7, f = n & 127;
    int k = threadIdx.x;
    float acc = 0.f;
    #pragma unroll 4
    for (int fp = 0; fp < DEH; fp++)
        acc += efcW[k * DEH + fp] * W1[(m * DEH + fp) * DD + f];
    g_B[n * 64 + k] = __uint_as_float(tf32_rna(acc));
    if (k == 0) {
        float b = b1[n];
        #pragma unroll 4
        for (int fp = 0; fp < DEH; fp++)
            b += efcb[fp] * W1[(m * DEH + fp) * DD + f];
        g_bb[n] = b;
    }
}

// ---------------- kernel B: tensor-core (mma.sync tf32) edge MLP -> g_eg ----------------
// 384 threads = 12 warps: warp (m = wid/4, r = wid%4) covers 32 rows x head m's 128 cols.
// smem floats: Bp [384][72] pair-packed = 27648 | epi 384 float2 = 768 | As 2x[128][68] = 17408
#define BP_STRIDE 72
#define A_STRIDE  68
#define A_BUF_F   (128 * A_STRIDE)          // 8704 floats
#define OFF_EPI   27648
#define OFF_A     (27648 + 768)
#define SMEM_MLP  ((27648 + 768 + 2 * A_BUF_F) * 4)

__global__ void __launch_bounds__(384, 1) k_mlp(const float* __restrict__ ef,
                                                const float* __restrict__ W2,
                                                const float* __restrict__ b2)
{
    extern __shared__ float sm[];
    float*  Bp  = sm;
    float2* epi = (float2*)(sm + OFF_EPI);
    float*  As  = sm + OFF_A;

    int tid = threadIdx.x;
    int wid = tid >> 5, lane = tid & 31;
    int g = lane >> 2, tig = lane & 3;
    int m = wid >> 2;          // head 0..2
    int r = wid & 3;           // row quarter 0..3
    int rowbase = r * 32;

    // pair-packed B: Bp[n*72 + kk*8 + t*2 + {0: col t, 1: col t+4}]
    for (int i = tid; i < 384 * 64; i += 384) {
        int n = i >> 6, k = i & 63;
        int kk = k >> 3, t = k & 7;
        int pos = (t < 4) ? (n * BP_STRIDE + kk * 8 + t * 2)
                          : (n * BP_STRIDE + kk * 8 + (t - 4) * 2 + 1);
        Bp[pos] = g_B[i];
    }
    for (int i = tid; i < 384; i += 384) epi[i] = make_float2(g_bb[i], __ldg(W2 + i));
    __syncthreads();

    float b2m = __ldg(b2 + m);

    // prologue: load first tile into buf 0
    int t0 = blockIdx.x;
    {
        const float* srcb = ef + (size_t)t0 * 8192;
        for (int c = tid; c < 2048; c += 384)
            cp16(As + (c >> 4) * A_STRIDE + (c & 15) * 4, srcb + c * 4);
    }
    CP_COMMIT;

    int buf = 0;
    for (int t = t0; t < NTILES; t += GRID_MLP) {
        int tn = t + GRID_MLP;
        if (tn < NTILES) {
            const float* srcb = ef + (size_t)tn * 8192;
            float* dstb = As + (buf ^ 1) * A_BUF_F;
            for (int c = tid; c < 2048; c += 384)
                cp16(dstb + (c >> 4) * A_STRIDE + (c & 15) * 4, srcb + c * 4);
        }
        CP_COMMIT;
        CP_WAIT1;
        __syncthreads();

        // ---- load A fragments: two m16 tiles (rows rowbase..+15, rowbase+16..+31) ----
        const float* A = As + buf * A_BUF_F;
        uint32_t a0[2][8], a1[2][8], a2[2][8], a3[2][8];
        #pragma unroll
        for (int rt = 0; rt < 2; rt++) {
            const float* r0p = A + (rowbase + rt * 16 + g) * A_STRIDE;
            const float* r1p = A + (rowbase + rt * 16 + g + 8) * A_STRIDE;
            #pragma unroll
            for (int kk = 0; kk < 8; kk++) {
                a0[rt][kk] = tf32_rna(r0p[kk * 8 + tig]);
                a2[rt][kk] = tf32_rna(r0p[kk * 8 + tig + 4]);
                a1[rt][kk] = tf32_rna(r1p[kk * 8 + tig]);
                a3[rt][kk] = tf32_rna(r1p[kk * 8 + tig + 4]);
            }
        }

        // ---- 16 n-tiles of head m; B fragment loaded once, used for both row-tiles ----
        float p0 = 0.f, p1 = 0.f, p2 = 0.f, p3 = 0.f;
        #pragma unroll 4
        for (int nt = 0; nt < 16; nt++) {
            int n0 = m * 128 + nt * 8;
            float c00 = 0.f, c01 = 0.f, c02 = 0.f, c03 = 0.f;
            float c10 = 0.f, c11 = 0.f, c12 = 0.f, c13 = 0.f;
            const float2* bp = (const float2*)(Bp + (n0 + g) * BP_STRIDE) + tig;
            #pragma unroll
            for (int kk = 0; kk < 8; kk++) {
                float2 bv = bp[kk * 4];
                uint32_t b0 = __float_as_uint(bv.x);
                uint32_t b1 = __float_as_uint(bv.y);
                mma_tf32(c00, c01, c02, c03, a0[0][kk], a1[0][kk], a2[0][kk], a3[0][kk], b0, b1);
                mma_tf32(c10, c11, c12, c13, a0[1][kk], a1[1][kk], a2[1][kk], a3[1][kk], b0, b1);
            }
            float2 e0 = epi[n0 + 2 * tig];
            float2 e1 = epi[n0 + 2 * tig + 1];
            p0 += fmaxf(c00 + e0.x, 0.f) * e0.y + fmaxf(c01 + e1.x, 0.f) * e1.y;
            p1 += fmaxf(c02 + e0.x, 0.f) * e0.y + fmaxf(c03 + e1.x, 0.f) * e1.y;
            p2 += fmaxf(c10 + e0.x, 0.f) * e0.y + fmaxf(c11 + e1.x, 0.f) * e1.y;
            p3 += fmaxf(c12 + e0.x, 0.f) * e0.y + fmaxf(c13 + e1.x, 0.f) * e1.y;
        }
        #pragma unroll
        for (int off = 1; off <= 2; off <<= 1) {
            p0 += __shfl_xor_sync(0xffffffffu, p0, off);
            p1 += __shfl_xor_sync(0xffffffffu, p1, off);
            p2 += __shfl_xor_sync(0xffffffffu, p2, off);
            p3 += __shfl_xor_sync(0xffffffffu, p3, off);
        }
        if (tig == 0) {
            int e = t * 128 + rowbase + g;
            float* dst = g_eg + (size_t)m * EE;
            dst[e]      = __expf(sigmoidf_(p0 + b2m));
            dst[e + 8]  = __expf(sigmoidf_(p1 + b2m));
            dst[e + 16] = __expf(sigmoidf_(p2 + b2m));
            dst[e + 24] = __expf(sigmoidf_(p3 + b2m));
        }
        __syncthreads();
        buf ^= 1;
    }
}

// ---------------- kernel C: scatter (warp per edge) ----------------
__global__ void __launch_bounds__(256) k_scatter(const int* __restrict__ src,
                                                 const int* __restrict__ dst)
{
    int gwarp = (blockIdx.x * blockDim.x + threadIdx.x) >> 5;
    int lane = threadIdx.x & 31;
    int nwarps = (gridDim.x * blockDim.x) >> 5;

    for (int e = gwarp; e < EE; e += nwarps) {
        int s = __ldg(src + e);
        int d = __ldg(dst + e);
        float4 hs = *(const float4*)&g_h[(size_t)s * DD + lane * 4];
        float4 hd = *(const float4*)&g_h[(size_t)d * DD + lane * 4];
        float pa = hs.x * hd.x + hs.y * hd.y + hs.z * hd.z + hs.w * hd.w;
        #pragma unroll
        for (int off = 16; off; off >>= 1) pa += __shfl_xor_sync(0xffffffffu, pa, off);
        float ea = __expf(pa);
        float e0 = g_eg[e], e1 = g_eg[EE + e], e2 = g_eg[2 * EE + e];

        if (lane == 0)
            atomicAdd((float4*)(g_z + d * 4), make_float4(ea, e0, e1, e2));

        float4* A = (float4*)(g_acc + (size_t)d * 512) + lane;
        atomicAdd(A,      make_float4(ea * hs.x, ea * hs.y, ea * hs.z, ea * hs.w));
        atomicAdd(A + 32, make_float4(e0 * hs.x, e0 * hs.y, e0 * hs.z, e0 * hs.w));
        atomicAdd(A + 64, make_float4(e1 * hs.x, e1 * hs.y, e1 * hs.z, e1 * hs.w));
        atomicAdd(A + 96, make_float4(e2 * hs.x, e2 * hs.y, e2 * hs.z, e2 * hs.w));
    }
}

// ---------------- kernel D: finalize per node ----------------
__global__ void __launch_bounds__(256, 2) k_final(const float* __restrict__ nf,
                                                  const float* __restrict__ outb,
                                                  const float* __restrict__ gW,
                                                  const float* __restrict__ gb,
                                                  float* __restrict__ out)
{
    extern __shared__ float sm[];
    float* Wsm = sm;            // 16384 floats
    float* xbb = sm + 16384;    // 8 warps * 8 nodes * 128 = 8192 floats
    int tid = threadIdx.x;
    int warp = tid >> 5, lane = tid & 31;
    float* xb = xbb + warp * 1024;
    int nbase = blockIdx.x * 64 + warp * 8;

    float4 acc[8];
    #pragma unroll
    for (int t = 0; t < 8; t++) acc[t] = make_float4(0.f, 0.f, 0.f, 0.f);

    for (int phph = 0; phph < 4; phph++) {
        __syncthreads();
        {
            const float4* src4 = (const float4*)(g_C + phph * 16384);
            float4* dst4 = (float4*)Wsm;
            #pragma unroll
            for (int i = 0; i < 16; i++) dst4[i * 256 + tid] = src4[i * 256 + tid];
        }
        #pragma unroll
        for (int t = 0; t < 8; t++) {
            int n = nbase + t;
            float4 v = make_float4(0.f, 0.f, 0.f, 0.f);
            float sc = 0.f;
            if (n < NN) {
                float za = g_z[n * 4];
                if (za > 0.f) {
                    float den = (phph == 0) ? za : g_z[n * 4 + phph];
                    sc = 1.f / (3.f * den);
                    v = *(const float4*)&g_acc[(size_t)n * 512 + phph * 128 + lane * 4];
                }
            }
            *(float4*)&xb[t * 128 + lane * 4] = make_float4(v.x * sc, v.y * sc, v.z * sc, v.w * sc);
        }
        __syncthreads();
        const float4* W4 = (const float4*)Wsm;
        #pragma unroll 4
        for (int k = 0; k < 128; k++) {
            float4 w = W4[k * 32 + lane];
            #pragma unroll
            for (int t = 0; t < 8; t++) {
                float v = xb[t * 128 + k];
                acc[t].x += v * w.x; acc[t].y += v * w.y;
                acc[t].z += v * w.z; acc[t].w += v * w.w;
            }
        }
    }

    float4 b4  = *(const float4*)&outb[lane * 4];
    float4 gw4 = *(const float4*)&gW[lane * 4];
    float gb0 = __ldg(gb);
    #pragma unroll
    for (int t = 0; t < 8; t++) {
        int n = nbase + t;
        if (n >= NN) break;
        bool ok = (g_z[n * 4] > 0.f);
        float4 pre = make_float4(fmaxf(acc[t].x + b4.x, 0.f), fmaxf(acc[t].y + b4.y, 0.f),
                                 fmaxf(acc[t].z + b4.z, 0.f), fmaxf(acc[t].w + b4.w, 0.f));
        float4 hv  = *(const float4*)&g_h[(size_t)n * DD + lane * 4];
        float4 ho  = ok ? pre : hv;
        float4 nfv = *(const float4*)&nf[(size_t)n * DD + lane * 4];
        float gp = nfv.x * gw4.x + nfv.y * gw4.y + nfv.z * gw4.z + nfv.w * gw4.w;
        #pragma unroll
        for (int off = 16; off; off >>= 1) gp += __shfl_xor_sync(0xffffffffu, gp, off);
        float gate = sigmoidf_(gp + gb0);
        float4 o = make_float4(gate * ho.x + (1.f - gate) * nfv.x,
                               gate * ho.y + (1.f - gate) * nfv.y,
                               gate * ho.z + (1.f - gate) * nfv.z,
                               gate * ho.w + (1.f - gate) * nfv.w);
        *(float4*)&out[(size_t)n * DD + lane * 4] = o;
    }
}

// ---------------- launcher ----------------
extern "C" void kernel_launch(void* const* d_in, const int* in_sizes, int n_in,
                              void* d_out, int out_size)
{
    const float* nf   = (const float*)d_in[0];
    const float* ef   = (const float*)d_in[1];
    const int*   src  = (const int*)  d_in[2];
    const int*   dst  = (const int*)  d_in[3];
    const float* natt = (const float*)d_in[4];
    const float* relW = (const float*)d_in[5];
    const float* W1   = (const float*)d_in[6];
    const float* b1   = (const float*)d_in[7];
    const float* W2   = (const float*)d_in[8];
    const float* b2   = (const float*)d_in[9];
    const float* nfcW = (const float*)d_in[10];
    const float* nfcb = (const float*)d_in[11];
    const float* efcW = (const float*)d_in[12];
    const float* efcb = (const float*)d_in[13];
    const float* outW = (const float*)d_in[14];
    const float* outb = (const float*)d_in[15];
    const float* gW   = (const float*)d_in[16];
    const float* gb   = (const float*)d_in[17];
    float* out = (float*)d_out;

    void *pAcc, *pZ;
    cudaGetSymbolAddress(&pAcc, g_acc);
    cudaGetSymbolAddress(&pZ,   g_z);
    cudaMemsetAsync(pAcc, 0, (size_t)NN * 512 * sizeof(float));
    cudaMemsetAsync(pZ,   0, (size_t)NN * 4 * sizeof(float));

    const int SMEM_A = (16384 + 128 + 8 * 128) * 4;
    const int SMEM_D = (16384 + 8192) * 4;
    cudaFuncSetAttribute(k_node_fc, cudaFuncAttributeMaxDynamicSharedMemorySize, SMEM_A);
    cudaFuncSetAttribute(k_mlp,     cudaFuncAttributeMaxDynamicSharedMemorySize, SMEM_MLP);
    cudaFuncSetAttribute(k_final,   cudaFuncAttributeMaxDynamicSharedMemorySize, SMEM_D);

    k_node_fc<<<(NN + 7) / 8, 256, SMEM_A>>>(nf, nfcW, nfcb);
    k_combine<<<512, 128>>>(natt, relW, outW);
    k_prepF<<<384, 64>>>(efcW, efcb, W1, b1);
    k_mlp<<<GRID_MLP, 384, SMEM_MLP>>>(ef, W2, b2);
    k_scatter<<<1184, 256>>>(src, dst);
    k_final<<<(NN + 63) / 64, 256, SMEM_D>>>(nf, outb, gW, gb, out);
}

// round 5
// speedup vs baseline: 2.9949x; 1.2824x over previous
#include <cuda_runtime.h>
#include <cuda_bf16.h>
#include <math.h>
#include <stdint.h>

#define NN   20000
#define NNP  20032
#define EE   320000
#define DD   128
#define DEH  64
#define NTILES (EE / 128)   // 2500
#define GRID_MLP 148
#define NB   64             // nodes per k_final CTA

// ---------------- scratch (device globals; no allocation allowed) ----------------
__device__ float g_h[NN * DD];                 // node_fc output h
__device__ float g_acc[(size_t)NNP * 512];     // per-node [P | Q0 | Q1 | Q2] (pre-scaled)
__device__ float g_za[NNP];                    // sum exp(a) per dst (mask)
__device__ float g_Ct_hi[4 * DD * DD];         // folded C, transposed [ph][out][k], tf32 hi
__device__ float g_Ct_lo[4 * DD * DD];         // tf32 lo residual
__device__ float g_eg4f[EE * 4];               // exp(sigmoid(g)) per edge, [e][m]
__device__ float g_B[384 * 64];                // folded MLP weights Gᵀ (tf32-rounded fp32)
__device__ float g_bb[384];                    // folded bias bb1
__device__ int   g_deg[NN];
__device__ int   g_off[NN];
__device__ int   g_cur[NN];
__device__ int2  g_epack[EE];                  // (src, e) sorted by dst

__device__ __forceinline__ float sigmoidf_(float x) { return 1.f / (1.f + __expf(-x)); }

__device__ __forceinline__ uint32_t smem_to_u32(const void* p) {
    uint32_t a;
    asm("{ .reg .u64 t; cvta.to.shared.u64 t, %1; cvt.u32.u64 %0, t; }" : "=r"(a) : "l"(p));
    return a;
}
__device__ __forceinline__ uint32_t tf32_rna(float x) {
    uint32_t r; asm("cvt.rna.tf32.f32 %0, %1;" : "=r"(r) : "f"(x)); return r;
}
__device__ __forceinline__ void mma_tf32(float& c0, float& c1, float& c2, float& c3,
                                         uint32_t a0, uint32_t a1, uint32_t a2, uint32_t a3,
                                         uint32_t b0, uint32_t b1) {
    asm volatile("mma.sync.aligned.m16n8k8.row.col.f32.tf32.tf32.f32 "
                 "{%0,%1,%2,%3}, {%4,%5,%6,%7}, {%8,%9}, {%0,%1,%2,%3};"
                 : "+f"(c0), "+f"(c1), "+f"(c2), "+f"(c3)
                 : "r"(a0), "r"(a1), "r"(a2), "r"(a3), "r"(b0), "r"(b1));
}
__device__ __forceinline__ void cp16(float* dst_smem, const float* src) {
    uint32_t d = smem_to_u32(dst_smem);
    asm volatile("cp.async.ca.shared.global [%0], [%1], 16;" :: "r"(d), "l"(src));
}
#define CP_COMMIT asm volatile("cp.async.commit_group;" ::: "memory")
#define CP_WAIT1  asm volatile("cp.async.wait_group 1;"  ::: "memory")

// ---------------- kernel A: h = nf @ node_fc_W + b ----------------
__global__ void __launch_bounds__(256) k_node_fc(const float* __restrict__ nf,
                                                 const float* __restrict__ W,
                                                 const float* __restrict__ b)
{
    extern __shared__ float sm[];
    float* Wsm = sm;                 // 16384
    float* bsm = sm + 16384;         // 128
    float* buf = sm + 16384 + 128;   // 8 * 128
    int tid = threadIdx.x;
    for (int i = tid; i < DD * DD; i += blockDim.x) Wsm[i] = W[i];
    if (tid < DD) bsm[tid] = b[tid];
    __syncthreads();

    int warp = tid >> 5, lane = tid & 31;
    int n = blockIdx.x * 8 + warp;
    if (n >= NN) return;
    float* wb = buf + warp * DD;
    float4 x = *(const float4*)&nf[n * DD + lane * 4];
    *(float4*)&wb[lane * 4] = x;
    __syncwarp();
    float4 acc = *(float4*)&bsm[lane * 4];
    const float4* W4 = (const float4*)Wsm;
    #pragma unroll 8
    for (int k = 0; k < DD; k++) {
        float v = wb[k];
        float4 w = W4[k * 32 + lane];
        acc.x += v * w.x; acc.y += v * w.y; acc.z += v * w.z; acc.w += v * w.w;
    }
    *(float4*)&g_h[n * DD + lane * 4] = acc;
}

// ---------------- kernel P1: fold C0 = Wsum@U_top, Cm = W_m@U_bot (transposed hi/lo) ----------------
__global__ void k_combine(const float* __restrict__ natt,
                          const float* __restrict__ relW,
                          const float* __restrict__ outW)
{
    __shared__ float row[DD];
    int i = blockIdx.x >> 7;          // phase 0..3
    int d = blockIdx.x & 127;         // k
    int c = threadIdx.x;              // output
    if (i == 0)
        row[c] = natt[d * DD + c] + natt[DD * DD + d * DD + c] + natt[2 * DD * DD + d * DD + c];
    else
        row[c] = relW[(i - 1) * DD * DD + d * DD + c];
    __syncthreads();
    const float* U = (i == 0) ? outW : outW + DD * DD;
    float acc = 0.f;
    #pragma unroll 8
    for (int f = 0; f < DD; f++) acc += row[f] * U[f * DD + c];
    float hi = __uint_as_float(tf32_rna(acc));
    float lo = __uint_as_float(tf32_rna(acc - hi));
    g_Ct_hi[i * DD * DD + c * DD + d] = hi;
    g_Ct_lo[i * DD * DD + c * DD + d] = lo;
}

// ---------------- kernel P2: fold G_m = efcW @ W1_m (tf32-rounded) + bias bb ----------------
__global__ void k_prepF(const float* __restrict__ efcW,
                        const float* __restrict__ efcb,
                        const float* __restrict__ W1,
                        const float* __restrict__ b1)
{
    int n = blockIdx.x;
    int m = n >> 7, f = n & 127;
    int k = threadIdx.x;
    float acc = 0.f;
    #pragma unroll 4
    for (int fp = 0; fp < DEH; fp++)
        acc += efcW[k * DEH + fp] * W1[(m * DEH + fp) * DD + f];
    g_B[n * 64 + k] = __uint_as_float(tf32_rna(acc));
    if (k == 0) {
        float b = b1[n];
        #pragma unroll 4
        for (int fp = 0; fp < DEH; fp++)
            b += efcb[fp] * W1[(m * DEH + fp) * DD + f];
        g_bb[n] = b;
    }
}

// ---------------- CSR build ----------------
__global__ void k_hist(const int* __restrict__ dst)
{
    int e = blockIdx.x * 256 + threadIdx.x;
    if (e < EE) atomicAdd(&g_deg[dst[e]], 1);
}

__global__ void __launch_bounds__(1024) k_scan()
{
    int tid = threadIdx.x;
    int lane = tid & 31, w = tid >> 5;
    int base = tid * 20;
    int loc[20]; int s = 0;
    #pragma unroll
    for (int j = 0; j < 20; j++) {
        int n = base + j;
        int d = (n < NN) ? g_deg[n] : 0;
        loc[j] = s; s += d;
    }
    int v = s;
    #pragma unroll
    for (int off = 1; off < 32; off <<= 1) {
        int u = __shfl_up_sync(0xffffffffu, v, off);
        if (lane >= off) v += u;
    }
    __shared__ int wsum[32];
    if (lane == 31) wsum[w] = v;
    __syncthreads();
    if (w == 0) {
        int t = wsum[lane];
        #pragma unroll
        for (int off = 1; off < 32; off <<= 1) {
            int u = __shfl_up_sync(0xffffffffu, t, off);
            if (lane >= off) t += u;
        }
        wsum[lane] = t;
    }
    __syncthreads();
    int excl = v - s + (w > 0 ? wsum[w - 1] : 0);
    #pragma unroll
    for (int j = 0; j < 20; j++) {
        int n = base + j;
        if (n < NN) { int o = excl + loc[j]; g_off[n] = o; g_cur[n] = o; }
    }
}

__global__ void k_fill(const int* __restrict__ src, const int* __restrict__ dst)
{
    int e = blockIdx.x * 256 + threadIdx.x;
    if (e < EE) {
        int d = dst[e];
        int pos = atomicAdd(&g_cur[d], 1);
        g_epack[pos] = make_int2(src[e], e);
    }
}

// ---------------- kernel B: tensor-core (mma.sync tf32) edge MLP -> g_eg4f ----------------
#define BP_STRIDE 72
#define A_STRIDE  68
#define A_BUF_F   (128 * A_STRIDE)          // 8704 floats
#define OFF_EPI   27648
#define OFF_A     (27648 + 768)
#define SMEM_MLP  ((27648 + 768 + 2 * A_BUF_F) * 4)

__global__ void __launch_bounds__(384, 1) k_mlp(const float* __restrict__ ef,
                                                const float* __restrict__ W2,
                                                const float* __restrict__ b2)
{
    extern __shared__ float sm[];
    float*  Bp  = sm;
    float2* epi = (float2*)(sm + OFF_EPI);
    float*  As  = sm + OFF_A;

    int tid = threadIdx.x;
    int wid = tid >> 5, lane = tid & 31;
    int g = lane >> 2, tig = lane & 3;
    int m = wid >> 2;          // head 0..2
    int r = wid & 3;           // row quarter 0..3
    int rowbase = r * 32;

    for (int i = tid; i < 384 * 64; i += 384) {
        int n = i >> 6, k = i & 63;
        int kk = k >> 3, t = k & 7;
        int pos = (t < 4) ? (n * BP_STRIDE + kk * 8 + t * 2)
                          : (n * BP_STRIDE + kk * 8 + (t - 4) * 2 + 1);
        Bp[pos] = g_B[i];
    }
    for (int i = tid; i < 384; i += 384) epi[i] = make_float2(g_bb[i], __ldg(W2 + i));
    __syncthreads();

    float b2m = __ldg(b2 + m);

    int t0 = blockIdx.x;
    {
        const float* srcb = ef + (size_t)t0 * 8192;
        for (int c = tid; c < 2048; c += 384)
            cp16(As + (c >> 4) * A_STRIDE + (c & 15) * 4, srcb + c * 4);
    }
    CP_COMMIT;

    int buf = 0;
    for (int t = t0; t < NTILES; t += GRID_MLP) {
        int tn = t + GRID_MLP;
        if (tn < NTILES) {
            const float* srcb = ef + (size_t)tn * 8192;
            float* dstb = As + (buf ^ 1) * A_BUF_F;
            for (int c = tid; c < 2048; c += 384)
                cp16(dstb + (c >> 4) * A_STRIDE + (c & 15) * 4, srcb + c * 4);
        }
        CP_COMMIT;
        CP_WAIT1;
        __syncthreads();

        const float* A = As + buf * A_BUF_F;
        uint32_t a0[2][8], a1[2][8], a2[2][8], a3[2][8];
        #pragma unroll
        for (int rt = 0; rt < 2; rt++) {
            const float* r0p = A + (rowbase + rt * 16 + g) * A_STRIDE;
            const float* r1p = A + (rowbase + rt * 16 + g + 8) * A_STRIDE;
            #pragma unroll
            for (int kk = 0; kk < 8; kk++) {
                a0[rt][kk] = tf32_rna(r0p[kk * 8 + tig]);
                a2[rt][kk] = tf32_rna(r0p[kk * 8 + tig + 4]);
                a1[rt][kk] = tf32_rna(r1p[kk * 8 + tig]);
                a3[rt][kk] = tf32_rna(r1p[kk * 8 + tig + 4]);
            }
        }

        float p0 = 0.f, p1 = 0.f, p2 = 0.f, p3 = 0.f;
        #pragma unroll 4
        for (int nt = 0; nt < 16; nt++) {
            int n0 = m * 128 + nt * 8;
            float c00 = 0.f, c01 = 0.f, c02 = 0.f, c03 = 0.f;
            float c10 = 0.f, c11 = 0.f, c12 = 0.f, c13 = 0.f;
            const float2* bp = (const float2*)(Bp + (n0 + g) * BP_STRIDE) + tig;
            #pragma unroll
            for (int kk = 0; kk < 8; kk++) {
                float2 bv = bp[kk * 4];
                uint32_t b0 = __float_as_uint(bv.x);
                uint32_t b1 = __float_as_uint(bv.y);
                mma_tf32(c00, c01, c02, c03, a0[0][kk], a1[0][kk], a2[0][kk], a3[0][kk], b0, b1);
                mma_tf32(c10, c11, c12, c13, a0[1][kk], a1[1][kk], a2[1][kk], a3[1][kk], b0, b1);
            }
            float2 e0 = epi[n0 + 2 * tig];
            float2 e1 = epi[n0 + 2 * tig + 1];
            p0 += fmaxf(c00 + e0.x, 0.f) * e0.y + fmaxf(c01 + e1.x, 0.f) * e1.y;
            p1 += fmaxf(c02 + e0.x, 0.f) * e0.y + fmaxf(c03 + e1.x, 0.f) * e1.y;
            p2 += fmaxf(c10 + e0.x, 0.f) * e0.y + fmaxf(c11 + e1.x, 0.f) * e1.y;
            p3 += fmaxf(c12 + e0.x, 0.f) * e0.y + fmaxf(c13 + e1.x, 0.f) * e1.y;
        }
        #pragma unroll
        for (int off = 1; off <= 2; off <<= 1) {
            p0 += __shfl_xor_sync(0xffffffffu, p0, off);
            p1 += __shfl_xor_sync(0xffffffffu, p1, off);
            p2 += __shfl_xor_sync(0xffffffffu, p2, off);
            p3 += __shfl_xor_sync(0xffffffffu, p3, off);
        }
        if (tig == 0) {
            int e = t * 128 + rowbase + g;
            g_eg4f[(e)      * 4 + m] = __expf(sigmoidf_(p0 + b2m));
            g_eg4f[(e + 8)  * 4 + m] = __expf(sigmoidf_(p1 + b2m));
            g_eg4f[(e + 16) * 4 + m] = __expf(sigmoidf_(p2 + b2m));
            g_eg4f[(e + 24) * 4 + m] = __expf(sigmoidf_(p3 + b2m));
        }
        __syncthreads();
        buf ^= 1;
    }
}

// ---------------- kernel C: gather (warp per dst node, no atomics) ----------------
__global__ void __launch_bounds__(256) k_gather()
{
    int gw = (blockIdx.x * 256 + threadIdx.x) >> 5;
    int lane = threadIdx.x & 31;
    int n = gw;
    if (n >= NN) return;

    int off = g_off[n];
    int deg = g_deg[n];
    float4 hd = *(const float4*)&g_h[(size_t)n * DD + lane * 4];

    float4 aP = make_float4(0.f,0.f,0.f,0.f), q0 = aP, q1 = aP, q2 = aP;
    float za = 0.f, z0 = 0.f, z1 = 0.f, z2 = 0.f;

    int j = 0;
    for (; j + 1 < deg; j += 2) {
        int2 se0 = __ldg(&g_epack[off + j]);
        int2 se1 = __ldg(&g_epack[off + j + 1]);
        float4 hsA = *(const float4*)&g_h[(size_t)se0.x * DD + lane * 4];
        float4 hsB = *(const float4*)&g_h[(size_t)se1.x * DD + lane * 4];
        float4 egA = *(const float4*)&g_eg4f[(size_t)se0.y * 4];
        float4 egB = *(const float4*)&g_eg4f[(size_t)se1.y * 4];
        float pa = hsA.x*hd.x + hsA.y*hd.y + hsA.z*hd.z + hsA.w*hd.w;
        float pb = hsB.x*hd.x + hsB.y*hd.y + hsB.z*hd.z + hsB.w*hd.w;
        #pragma unroll
        for (int o = 16; o; o >>= 1) {
            pa += __shfl_xor_sync(0xffffffffu, pa, o);
            pb += __shfl_xor_sync(0xffffffffu, pb, o);
        }
        float eaA = __expf(pa), eaB = __expf(pb);
        za += eaA + eaB;
        z0 += egA.x + egB.x; z1 += egA.y + egB.y; z2 += egA.z + egB.z;
        aP.x += eaA*hsA.x + eaB*hsB.x; aP.y += eaA*hsA.y + eaB*hsB.y;
        aP.z += eaA*hsA.z + eaB*hsB.z; aP.w += eaA*hsA.w + eaB*hsB.w;
        q0.x += egA.x*hsA.x + egB.x*hsB.x; q0.y += egA.x*hsA.y + egB.x*hsB.y;
        q0.z += egA.x*hsA.z + egB.x*hsB.z; q0.w += egA.x*hsA.w + egB.x*hsB.w;
        q1.x += egA.y*hsA.x + egB.y*hsB.x; q1.y += egA.y*hsA.y + egB.y*hsB.y;
        q1.z += egA.y*hsA.z + egB.y*hsB.z; q1.w += egA.y*hsA.w + egB.y*hsB.w;
        q2.x += egA.z*hsA.x + egB.z*hsB.x; q2.y += egA.z*hsA.y + egB.z*hsB.y;
        q2.z += egA.z*hsA.z + egB.z*hsB.z; q2.w += egA.z*hsA.w + egB.z*hsB.w;
    }
    if (j < deg) {
        int2 se = __ldg(&g_epack[off + j]);
        float4 hs = *(const float4*)&g_h[(size_t)se.x * DD + lane * 4];
        float4 eg = *(const float4*)&g_eg4f[(size_t)se.y * 4];
        float pa = hs.x*hd.x + hs.y*hd.y + hs.z*hd.z + hs.w*hd.w;
        #pragma unroll
        for (int o = 16; o; o >>= 1) pa += __shfl_xor_sync(0xffffffffu, pa, o);
        float ea = __expf(pa);
        za += ea; z0 += eg.x; z1 += eg.y; z2 += eg.z;
        aP.x += ea*hs.x; aP.y += ea*hs.y; aP.z += ea*hs.z; aP.w += ea*hs.w;
        q0.x += eg.x*hs.x; q0.y += eg.x*hs.y; q0.z += eg.x*hs.z; q0.w += eg.x*hs.w;
        q1.x += eg.y*hs.x; q1.y += eg.y*hs.y; q1.z += eg.y*hs.z; q1.w += eg.y*hs.w;
        q2.x += eg.z*hs.x; q2.y += eg.z*hs.y; q2.z += eg.z*hs.z; q2.w += eg.z*hs.w;
    }

    float sP = 0.f, s0 = 0.f, s1 = 0.f, s2 = 0.f;
    if (deg > 0) {
        sP = 1.f / (3.f * za); s0 = 1.f / (3.f * z0);
        s1 = 1.f / (3.f * z1); s2 = 1.f / (3.f * z2);
    }
    float* base = g_acc + (size_t)n * 512;
    *(float4*)(base + lane * 4)       = make_float4(aP.x*sP, aP.y*sP, aP.z*sP, aP.w*sP);
    *(float4*)(base + 128 + lane * 4) = make_float4(q0.x*s0, q0.y*s0, q0.z*s0, q0.w*s0);
    *(float4*)(base + 256 + lane * 4) = make_float4(q1.x*s1, q1.y*s1, q1.z*s1, q1.w*s1);
    *(float4*)(base + 384 + lane * 4) = make_float4(q2.x*s2, q2.y*s2, q2.z*s2, q2.w*s2);
    if (lane == 0) g_za[n] = (deg > 0) ? za : 0.f;
}

// ---------------- kernel D: finalize per node (tf32 mma, weights hi/lo) ----------------
// smem: WsT [128][132] = 16896 floats | As [64][132] = 8448 floats  -> 101376 B
#define FW_STRIDE 132
#define SMEM_FIN  ((16896 + 8448) * 4)

__global__ void __launch_bounds__(256, 2) k_final(const float* __restrict__ nf,
                                                  const float* __restrict__ outb,
                                                  const float* __restrict__ gW,
                                                  const float* __restrict__ gb,
                                                  float* __restrict__ out)
{
    extern __shared__ float sm[];
    float* WsT = sm;
    float* As  = sm + 16896;

    int tid = threadIdx.x;
    int w = tid >> 5, lane = tid & 31;
    int g = lane >> 2, tig = lane & 3;
    int nbase = blockIdx.x * NB;

    float c[8][4];
    #pragma unroll
    for (int i = 0; i < 8; i++) { c[i][0]=0.f; c[i][1]=0.f; c[i][2]=0.f; c[i][3]=0.f; }

    for (int ph = 0; ph < 4; ph++) {
        __syncthreads();
        // stage node data (tf32-rounded)
        for (int q = tid; q < 2048; q += 256) {
            int nn = q >> 5, kq = q & 31;
            int gn = nbase + nn;
            float4 v = make_float4(0.f,0.f,0.f,0.f);
            if (gn < NN) v = *(const float4*)&g_acc[(size_t)gn * 512 + ph * 128 + kq * 4];
            v.x = __uint_as_float(tf32_rna(v.x)); v.y = __uint_as_float(tf32_rna(v.y));
            v.z = __uint_as_float(tf32_rna(v.z)); v.w = __uint_as_float(tf32_rna(v.w));
            *(float4*)&As[nn * FW_STRIDE + kq * 4] = v;
        }
        #pragma unroll
        for (int pass = 0; pass < 2; pass++) {
            __syncthreads();
            const float* Csrc = (pass ? g_Ct_lo : g_Ct_hi) + ph * 16384;
            for (int q = tid; q < 4096; q += 256) {
                int rr = q >> 5, kq = q & 31;
                *(float4*)&WsT[rr * FW_STRIDE + kq * 4] = *(const float4*)&Csrc[rr * 128 + kq * 4];
            }
            __syncthreads();
            uint32_t a0[16], a1[16], a2[16], a3[16];
            const float* w0 = &WsT[(w * 16 + g) * FW_STRIDE];
            const float* w1 = &WsT[(w * 16 + 8 + g) * FW_STRIDE];
            #pragma unroll
            for (int kk = 0; kk < 16; kk++) {
                a0[kk] = __float_as_uint(w0[kk * 8 + tig]);
                a2[kk] = __float_as_uint(w0[kk * 8 + tig + 4]);
                a1[kk] = __float_as_uint(w1[kk * 8 + tig]);
                a3[kk] = __float_as_uint(w1[kk * 8 + tig + 4]);
            }
            #pragma unroll
            for (int nt = 0; nt < 8; nt++) {
                const float* bp = &As[(nt * 8 + g) * FW_STRIDE];
                #pragma unroll
                for (int kk = 0; kk < 16; kk++) {
                    uint32_t b0 = __float_as_uint(bp[kk * 8 + tig]);
                    uint32_t b1 = __float_as_uint(bp[kk * 8 + tig + 4]);
                    mma_tf32(c[nt][0], c[nt][1], c[nt][2], c[nt][3],
                             a0[kk], a1[kk], a2[kk], a3[kk], b0, b1);
                }
            }
        }
    }

    // stage result [node][output] into As
    __syncthreads();
    #pragma unroll
    for (int nt = 0; nt < 8; nt++) {
        int n0 = nt * 8 + tig * 2;
        As[n0 * FW_STRIDE + w * 16 + g]           = c[nt][0];
        As[(n0 + 1) * FW_STRIDE + w * 16 + g]     = c[nt][1];
        As[n0 * FW_STRIDE + w * 16 + 8 + g]       = c[nt][2];
        As[(n0 + 1) * FW_STRIDE + w * 16 + 8 + g] = c[nt][3];
    }
    __syncthreads();

    float4 b4  = *(const float4*)&outb[lane * 4];
    float4 gw4 = *(const float4*)&gW[lane * 4];
    float gb0 = __ldg(gb);
    #pragma unroll
    for (int t = 0; t < 8; t++) {
        int i = w * 8 + t;
        int n = nbase + i;
        if (n >= NN) break;
        float4 vv = *(const float4*)&As[i * FW_STRIDE + lane * 4];
        bool ok = (g_za[n] > 0.f);
        float4 pre = make_float4(fmaxf(vv.x + b4.x, 0.f), fmaxf(vv.y + b4.y, 0.f),
                                 fmaxf(vv.z + b4.z, 0.f), fmaxf(vv.w + b4.w, 0.f));
        float4 hv  = *(const float4*)&g_h[(size_t)n * DD + lane * 4];
        float4 ho  = ok ? pre : hv;
        float4 nfv = *(const float4*)&nf[(size_t)n * DD + lane * 4];
        float gp = nfv.x * gw4.x + nfv.y * gw4.y + nfv.z * gw4.z + nfv.w * gw4.w;
        #pragma unroll
        for (int o = 16; o; o >>= 1) gp += __shfl_xor_sync(0xffffffffu, gp, o);
        float gate = sigmoidf_(gp + gb0);
        float4 oo = make_float4(gate * ho.x + (1.f - gate) * nfv.x,
                                gate * ho.y + (1.f - gate) * nfv.y,
                                gate * ho.z + (1.f - gate) * nfv.z,
                                gate * ho.w + (1.f - gate) * nfv.w);
        *(float4*)&out[(size_t)n * DD + lane * 4] = oo;
    }
}

// ---------------- launcher ----------------
extern "C" void kernel_launch(void* const* d_in, const int* in_sizes, int n_in,
                              void* d_out, int out_size)
{
    const float* nf   = (const float*)d_in[0];
    const float* ef   = (const float*)d_in[1];
    const int*   src  = (const int*)  d_in[2];
    const int*   dst  = (const int*)  d_in[3];
    const float* natt = (const float*)d_in[4];
    const float* relW = (const float*)d_in[5];
    const float* W1   = (const float*)d_in[6];
    const float* b1   = (const float*)d_in[7];
    const float* W2   = (const float*)d_in[8];
    const float* b2   = (const float*)d_in[9];
    const float* nfcW = (const float*)d_in[10];
    const float* nfcb = (const float*)d_in[11];
    const float* efcW = (const float*)d_in[12];
    const float* efcb = (const float*)d_in[13];
    const float* outW = (const float*)d_in[14];
    const float* outb = (const float*)d_in[15];
    const float* gW   = (const float*)d_in[16];
    const float* gb   = (const float*)d_in[17];
    float* out = (float*)d_out;

    void* pDeg;
    cudaGetSymbolAddress(&pDeg, g_deg);
    cudaMemsetAsync(pDeg, 0, NN * sizeof(int));

    const int SMEM_A = (16384 + 128 + 8 * 128) * 4;
    cudaFuncSetAttribute(k_node_fc, cudaFuncAttributeMaxDynamicSharedMemorySize, SMEM_A);
    cudaFuncSetAttribute(k_mlp,     cudaFuncAttributeMaxDynamicSharedMemorySize, SMEM_MLP);
    cudaFuncSetAttribute(k_final,   cudaFuncAttributeMaxDynamicSharedMemorySize, SMEM_FIN);

    k_node_fc<<<(NN + 7) / 8, 256, SMEM_A>>>(nf, nfcW, nfcb);
    k_combine<<<512, 128>>>(natt, relW, outW);
    k_prepF<<<384, 64>>>(efcW, efcb, W1, b1);
    k_hist<<<(EE + 255) / 256, 256>>>(dst);
    k_scan<<<1, 1024>>>();
    k_fill<<<(EE + 255) / 256, 256>>>(src, dst);
    k_mlp<<<GRID_MLP, 384, SMEM_MLP>>>(ef, W2, b2);
    k_gather<<<(NN + 7) / 8, 256>>>();
    k_final<<<(NN + NB - 1) / NB, 256, SMEM_FIN>>>(nf, outb, gW, gb, out);
}

// round 6
// speedup vs baseline: 3.2058x; 1.0704x over previous
#include <cuda_runtime.h>
#include <cuda_bf16.h>
#include <math.h>
#include <stdint.h>

#define NN   20000
#define NNP  20032
#define EE   320000
#define DD   128
#define DEH  64
#define NTILES (EE / 128)   // 2500
#define GRID_MLP 148
#define NB   64             // nodes per k_final CTA

// ---------------- scratch (device globals; no allocation allowed) ----------------
__device__ float g_h[NN * DD];                 // node_fc output h
__device__ float g_acc[(size_t)NNP * 512];     // per-node [P | Q0 | Q1 | Q2] (pre-scaled)
__device__ float g_za[NNP];                    // sum exp(a) per dst (mask)
__device__ float g_Ct_hi[4 * DD * DD];         // folded C, transposed [ph][out][k], tf32 hi
__device__ float g_Ct_lo[4 * DD * DD];         // tf32 lo residual
__device__ float g_Wt_hi[DD * DD];             // node_fc W transposed [out][k], tf32 hi
__device__ float g_Wt_lo[DD * DD];             // tf32 lo residual
__device__ float g_eg4f[EE * 4];               // exp(sigmoid(g)) per edge, [e][m]
__device__ float g_B[384 * 64];                // folded MLP weights Gᵀ (tf32-rounded fp32)
__device__ float g_bb[384];                    // folded bias bb1
__device__ int   g_deg[NN];
__device__ int   g_off[NN];
__device__ int   g_cur[NN];
__device__ int2  g_epack[EE];                  // (src, e) sorted by dst

__device__ __forceinline__ float sigmoidf_(float x) { return 1.f / (1.f + __expf(-x)); }

__device__ __forceinline__ uint32_t smem_to_u32(const void* p) {
    uint32_t a;
    asm("{ .reg .u64 t; cvta.to.shared.u64 t, %1; cvt.u32.u64 %0, t; }" : "=r"(a) : "l"(p));
    return a;
}
__device__ __forceinline__ uint32_t tf32_rna(float x) {
    uint32_t r; asm("cvt.rna.tf32.f32 %0, %1;" : "=r"(r) : "f"(x)); return r;
}
__device__ __forceinline__ float tf32f(float x) { return __uint_as_float(tf32_rna(x)); }
__device__ __forceinline__ void mma_tf32(float& c0, float& c1, float& c2, float& c3,
                                         uint32_t a0, uint32_t a1, uint32_t a2, uint32_t a3,
                                         uint32_t b0, uint32_t b1) {
    asm volatile("mma.sync.aligned.m16n8k8.row.col.f32.tf32.tf32.f32 "
                 "{%0,%1,%2,%3}, {%4,%5,%6,%7}, {%8,%9}, {%0,%1,%2,%3};"
                 : "+f"(c0), "+f"(c1), "+f"(c2), "+f"(c3)
                 : "r"(a0), "r"(a1), "r"(a2), "r"(a3), "r"(b0), "r"(b1));
}
__device__ __forceinline__ void cp16(float* dst_smem, const float* src) {
    uint32_t d = smem_to_u32(dst_smem);
    asm volatile("cp.async.ca.shared.global [%0], [%1], 16;" :: "r"(d), "l"(src));
}
#define CP_COMMIT asm volatile("cp.async.commit_group;" ::: "memory")
#define CP_WAIT1  asm volatile("cp.async.wait_group 1;"  ::: "memory")

// ---------------- prep: node_fc weight transpose + tf32 hi/lo split ----------------
__global__ void k_prepW(const float* __restrict__ W)
{
    int k = blockIdx.x, c = threadIdx.x;
    float v = W[k * DD + c];
    float hi = tf32f(v);
    g_Wt_hi[c * DD + k] = hi;
    g_Wt_lo[c * DD + k] = tf32f(v - hi);
}

// ---------------- kernel A: h = nf @ node_fc_W + b  (tf32 mma, 3-pass compensated) ----------------
// smem: Ws [128][132] | As [128][132] | bias 128  -> 135,680 B
#define NF_STRIDE 132
#define SMEM_NFC ((16896 * 2 + 128) * 4)

__global__ void __launch_bounds__(256, 1) k_node_fc(const float* __restrict__ nf,
                                                    const float* __restrict__ b)
{
    extern __shared__ float sm[];
    float* Ws  = sm;
    float* As  = sm + 16896;
    float* bsm = sm + 2 * 16896;

    int tid = threadIdx.x;
    int w = tid >> 5, lane = tid & 31;
    int g = lane >> 2, tig = lane & 3;
    int nbase = blockIdx.x * 128;
    if (tid < 128) bsm[tid] = b[tid];

    float c[16][4];
    #pragma unroll
    for (int i = 0; i < 16; i++) { c[i][0]=0.f; c[i][1]=0.f; c[i][2]=0.f; c[i][3]=0.f; }

    #pragma unroll
    for (int pass = 0; pass < 3; pass++) {
        __syncthreads();
        if (pass != 1) {   // stage A: hi on pass 0, lo on pass 2 (pass 1 reuses hi)
            bool lo = (pass == 2);
            for (int q = tid; q < 4096; q += 256) {
                int n = q >> 5, kq = q & 31;
                int gn = nbase + n;
                float4 v = make_float4(0.f,0.f,0.f,0.f);
                if (gn < NN) v = *(const float4*)&nf[(size_t)gn * DD + kq * 4];
                float4 o;
                if (!lo) o = make_float4(tf32f(v.x), tf32f(v.y), tf32f(v.z), tf32f(v.w));
                else     o = make_float4(tf32f(v.x - tf32f(v.x)), tf32f(v.y - tf32f(v.y)),
                                         tf32f(v.z - tf32f(v.z)), tf32f(v.w - tf32f(v.w)));
                *(float4*)&As[n * NF_STRIDE + kq * 4] = o;
            }
        }
        const float* Wsrc = (pass == 1) ? g_Wt_lo : g_Wt_hi;
        for (int q = tid; q < 4096; q += 256) {
            int rr = q >> 5, kq = q & 31;
            *(float4*)&Ws[rr * NF_STRIDE + kq * 4] = *(const float4*)&Wsrc[rr * DD + kq * 4];
        }
        __syncthreads();

        uint32_t a0[16], a1[16], a2[16], a3[16];
        const float* w0 = &Ws[(w * 16 + g) * NF_STRIDE];
        const float* w1 = &Ws[(w * 16 + 8 + g) * NF_STRIDE];
        #pragma unroll
        for (int kk = 0; kk < 16; kk++) {
            a0[kk] = __float_as_uint(w0[kk * 8 + tig]);
            a2[kk] = __float_as_uint(w0[kk * 8 + tig + 4]);
            a1[kk] = __float_as_uint(w1[kk * 8 + tig]);
            a3[kk] = __float_as_uint(w1[kk * 8 + tig + 4]);
        }
        #pragma unroll
        for (int nt = 0; nt < 16; nt++) {
            const float* bp = &As[(nt * 8 + g) * NF_STRIDE];
            #pragma unroll
            for (int kk = 0; kk < 16; kk++) {
                uint32_t b0 = __float_as_uint(bp[kk * 8 + tig]);
                uint32_t b1 = __float_as_uint(bp[kk * 8 + tig + 4]);
                mma_tf32(c[nt][0], c[nt][1], c[nt][2], c[nt][3],
                         a0[kk], a1[kk], a2[kk], a3[kk], b0, b1);
            }
        }
    }

    __syncthreads();
    #pragma unroll
    for (int nt = 0; nt < 16; nt++) {
        int n0 = nt * 8 + tig * 2;
        As[n0 * NF_STRIDE + w * 16 + g]           = c[nt][0];
        As[(n0 + 1) * NF_STRIDE + w * 16 + g]     = c[nt][1];
        As[n0 * NF_STRIDE + w * 16 + 8 + g]       = c[nt][2];
        As[(n0 + 1) * NF_STRIDE + w * 16 + 8 + g] = c[nt][3];
    }
    __syncthreads();
    for (int q = tid; q < 4096; q += 256) {
        int n = q >> 5, kq = q & 31;
        int gn = nbase + n;
        if (gn < NN) {
            float4 v = *(const float4*)&As[n * NF_STRIDE + kq * 4];
            float4 bb = *(const float4*)&bsm[kq * 4];
            *(float4*)&g_h[(size_t)gn * DD + kq * 4] =
                make_float4(v.x + bb.x, v.y + bb.y, v.z + bb.z, v.w + bb.w);
        }
    }
}

// ---------------- kernel P1: fold C0 = Wsum@U_top, Cm = W_m@U_bot (transposed hi/lo) ----------------
__global__ void k_combine(const float* __restrict__ natt,
                          const float* __restrict__ relW,
                          const float* __restrict__ outW)
{
    __shared__ float row[DD];
    int i = blockIdx.x >> 7;
    int d = blockIdx.x & 127;
    int c = threadIdx.x;
    if (i == 0)
        row[c] = natt[d * DD + c] + natt[DD * DD + d * DD + c] + natt[2 * DD * DD + d * DD + c];
    else
        row[c] = relW[(i - 1) * DD * DD + d * DD + c];
    __syncthreads();
    const float* U = (i == 0) ? outW : outW + DD * DD;
    float acc = 0.f;
    #pragma unroll 8
    for (int f = 0; f < DD; f++) acc += row[f] * U[f * DD + c];
    float hi = tf32f(acc);
    g_Ct_hi[i * DD * DD + c * DD + d] = hi;
    g_Ct_lo[i * DD * DD + c * DD + d] = tf32f(acc - hi);
}

// ---------------- kernel P2: fold G_m = efcW @ W1_m (tf32-rounded) + bias bb ----------------
__global__ void k_prepF(const float* __restrict__ efcW,
                        const float* __restrict__ efcb,
                        const float* __restrict__ W1,
                        const float* __restrict__ b1)
{
    int n = blockIdx.x;
    int m = n >> 7, f = n & 127;
    int k = threadIdx.x;
    float acc = 0.f;
    #pragma unroll 4
    for (int fp = 0; fp < DEH; fp++)
        acc += efcW[k * DEH + fp] * W1[(m * DEH + fp) * DD + f];
    g_B[n * 64 + k] = tf32f(acc);
    if (k == 0) {
        float b = b1[n];
        #pragma unroll 4
        for (int fp = 0; fp < DEH; fp++)
            b += efcb[fp] * W1[(m * DEH + fp) * DD + f];
        g_bb[n] = b;
    }
}

// ---------------- CSR build ----------------
__global__ void k_hist(const int* __restrict__ dst)
{
    int e = blockIdx.x * 256 + threadIdx.x;
    if (e < EE) atomicAdd(&g_deg[dst[e]], 1);
}

__global__ void __launch_bounds__(1024) k_scan()
{
    int tid = threadIdx.x;
    int lane = tid & 31, w = tid >> 5;
    int base = tid * 20;
    int loc[20]; int s = 0;
    #pragma unroll
    for (int j = 0; j < 20; j++) {
        int n = base + j;
        int d = (n < NN) ? g_deg[n] : 0;
        loc[j] = s; s += d;
    }
    int v = s;
    #pragma unroll
    for (int off = 1; off < 32; off <<= 1) {
        int u = __shfl_up_sync(0xffffffffu, v, off);
        if (lane >= off) v += u;
    }
    __shared__ int wsum[32];
    if (lane == 31) wsum[w] = v;
    __syncthreads();
    if (w == 0) {
        int t = wsum[lane];
        #pragma unroll
        for (int off = 1; off < 32; off <<= 1) {
            int u = __shfl_up_sync(0xffffffffu, t, off);
            if (lane >= off) t += u;
        }
        wsum[lane] = t;
    }
    __syncthreads();
    int excl = v - s + (w > 0 ? wsum[w - 1] : 0);
    #pragma unroll
    for (int j = 0; j < 20; j++) {
        int n = base + j;
        if (n < NN) { int o = excl + loc[j]; g_off[n] = o; g_cur[n] = o; }
    }
}

__global__ void k_fill(const int* __restrict__ src, const int* __restrict__ dst)
{
    int e = blockIdx.x * 256 + threadIdx.x;
    if (e < EE) {
        int d = dst[e];
        int pos = atomicAdd(&g_cur[d], 1);
        g_epack[pos] = make_int2(src[e], e);
    }
}

// ---------------- kernel B: tensor-core (mma.sync tf32) edge MLP -> g_eg4f ----------------
// 768 threads = 24 warps: warp (m = wid/8, r = wid%8) covers rows r*16..+15 x head m's 128 cols.
#define BP_STRIDE 72
#define A_STRIDE  68
#define A_BUF_F   (128 * A_STRIDE)          // 8704 floats
#define OFF_EPI   27648
#define OFF_A     (27648 + 768)
#define SMEM_MLP  ((27648 + 768 + 2 * A_BUF_F) * 4)

__global__ void __launch_bounds__(768, 1) k_mlp(const float* __restrict__ ef,
                                                const float* __restrict__ W2,
                                                const float* __restrict__ b2)
{
    extern __shared__ float sm[];
    float*  Bp  = sm;
    float2* epi = (float2*)(sm + OFF_EPI);
    float*  As  = sm + OFF_A;

    int tid = threadIdx.x;
    int wid = tid >> 5, lane = tid & 31;
    int g = lane >> 2, tig = lane & 3;
    int m = wid >> 3;          // head 0..2
    int r = wid & 7;           // row slice 0..7
    int rowbase = r * 16;

    for (int i = tid; i < 384 * 64; i += 768) {
        int n = i >> 6, k = i & 63;
        int kk = k >> 3, t = k & 7;
        int pos = (t < 4) ? (n * BP_STRIDE + kk * 8 + t * 2)
                          : (n * BP_STRIDE + kk * 8 + (t - 4) * 2 + 1);
        Bp[pos] = g_B[i];
    }
    if (tid < 384) epi[tid] = make_float2(g_bb[tid], __ldg(W2 + tid));
    __syncthreads();

    float b2m = __ldg(b2 + m);

    int t0 = blockIdx.x;
    {
        const float* srcb = ef + (size_t)t0 * 8192;
        for (int c = tid; c < 2048; c += 768)
            cp16(As + (c >> 4) * A_STRIDE + (c & 15) * 4, srcb + c * 4);
    }
    CP_COMMIT;

    int buf = 0;
    for (int t = t0; t < NTILES; t += GRID_MLP) {
        int tn = t + GRID_MLP;
        if (tn < NTILES) {
            const float* srcb = ef + (size_t)tn * 8192;
            float* dstb = As + (buf ^ 1) * A_BUF_F;
            for (int c = tid; c < 2048; c += 768)
                cp16(dstb + (c >> 4) * A_STRIDE + (c & 15) * 4, srcb + c * 4);
        }
        CP_COMMIT;
        CP_WAIT1;
        __syncthreads();

        const float* A = As + buf * A_BUF_F;
        const float* r0p = A + (rowbase + g) * A_STRIDE;
        const float* r1p = A + (rowbase + g + 8) * A_STRIDE;
        uint32_t a0[8], a1[8], a2[8], a3[8];
        #pragma unroll
        for (int kk = 0; kk < 8; kk++) {
            a0[kk] = tf32_rna(r0p[kk * 8 + tig]);
            a2[kk] = tf32_rna(r0p[kk * 8 + tig + 4]);
            a1[kk] = tf32_rna(r1p[kk * 8 + tig]);
            a3[kk] = tf32_rna(r1p[kk * 8 + tig + 4]);
        }

        float p0 = 0.f, p1 = 0.f;
        #pragma unroll 4
        for (int nt = 0; nt < 16; nt++) {
            int n0 = m * 128 + nt * 8;
            float c0 = 0.f, c1 = 0.f, c2 = 0.f, c3 = 0.f;
            const float2* bp = (const float2*)(Bp + (n0 + g) * BP_STRIDE) + tig;
            #pragma unroll
            for (int kk = 0; kk < 8; kk++) {
                float2 bv = bp[kk * 4];
                uint32_t b0 = __float_as_uint(bv.x);
                uint32_t b1 = __float_as_uint(bv.y);
                mma_tf32(c0, c1, c2, c3, a0[kk], a1[kk], a2[kk], a3[kk], b0, b1);
            }
            float2 e0 = epi[n0 + 2 * tig];
            float2 e1 = epi[n0 + 2 * tig + 1];
            p0 += fmaxf(c0 + e0.x, 0.f) * e0.y + fmaxf(c1 + e1.x, 0.f) * e1.y;
            p1 += fmaxf(c2 + e0.x, 0.f) * e0.y + fmaxf(c3 + e1.x, 0.f) * e1.y;
        }
        #pragma unroll
        for (int off = 1; off <= 2; off <<= 1) {
            p0 += __shfl_xor_sync(0xffffffffu, p0, off);
            p1 += __shfl_xor_sync(0xffffffffu, p1, off);
        }
        if (tig == 0) {
            int e = t * 128 + rowbase + g;
            g_eg4f[(e)     * 4 + m] = __expf(sigmoidf_(p0 + b2m));
            g_eg4f[(e + 8) * 4 + m] = __expf(sigmoidf_(p1 + b2m));
        }
        __syncthreads();
        buf ^= 1;
    }
}

// ---------------- kernel C: gather (warp per dst node, no atomics, unroll 4) ----------------
__global__ void __launch_bounds__(256) k_gather()
{
    int n = (blockIdx.x * 256 + threadIdx.x) >> 5;
    int lane = threadIdx.x & 31;
    if (n >= NN) return;

    int off = g_off[n];
    int deg = g_deg[n];
    float4 hd = *(const float4*)&g_h[(size_t)n * DD + lane * 4];

    float4 aP = make_float4(0.f,0.f,0.f,0.f), q0 = aP, q1 = aP, q2 = aP;
    float za = 0.f, z0 = 0.f, z1 = 0.f, z2 = 0.f;

    int j = 0;
    for (; j + 3 < deg; j += 4) {
        float4 hs[4], eg[4]; float p[4];
        #pragma unroll
        for (int u = 0; u < 4; u++) {
            int2 se = __ldg(&g_epack[off + j + u]);
            hs[u] = *(const float4*)&g_h[(size_t)se.x * DD + lane * 4];
            eg[u] = *(const float4*)&g_eg4f[(size_t)se.y * 4];
            p[u] = hs[u].x*hd.x + hs[u].y*hd.y + hs[u].z*hd.z + hs[u].w*hd.w;
        }
        #pragma unroll
        for (int o = 16; o; o >>= 1) {
            #pragma unroll
            for (int u = 0; u < 4; u++) p[u] += __shfl_xor_sync(0xffffffffu, p[u], o);
        }
        #pragma unroll
        for (int u = 0; u < 4; u++) {
            float ea = __expf(p[u]);
            za += ea; z0 += eg[u].x; z1 += eg[u].y; z2 += eg[u].z;
            aP.x += ea*hs[u].x; aP.y += ea*hs[u].y; aP.z += ea*hs[u].z; aP.w += ea*hs[u].w;
            q0.x += eg[u].x*hs[u].x; q0.y += eg[u].x*hs[u].y; q0.z += eg[u].x*hs[u].z; q0.w += eg[u].x*hs[u].w;
            q1.x += eg[u].y*hs[u].x; q1.y += eg[u].y*hs[u].y; q1.z += eg[u].y*hs[u].z; q1.w += eg[u].y*hs[u].w;
            q2.x += eg[u].z*hs[u].x; q2.y += eg[u].z*hs[u].y; q2.z += eg[u].z*hs[u].z; q2.w += eg[u].z*hs[u].w;
        }
    }
    for (; j < deg; j++) {
        int2 se = __ldg(&g_epack[off + j]);
        float4 hs = *(const float4*)&g_h[(size_t)se.x * DD + lane * 4];
        float4 eg = *(const float4*)&g_eg4f[(size_t)se.y * 4];
        float pa = hs.x*hd.x + hs.y*hd.y + hs.z*hd.z + hs.w*hd.w;
        #pragma unroll
        for (int o = 16; o; o >>= 1) pa += __shfl_xor_sync(0xffffffffu, pa, o);
        float ea = __expf(pa);
        za += ea; z0 += eg.x; z1 += eg.y; z2 += eg.z;
        aP.x += ea*hs.x; aP.y += ea*hs.y; aP.z += ea*hs.z; aP.w += ea*hs.w;
        q0.x += eg.x*hs.x; q0.y += eg.x*hs.y; q0.z += eg.x*hs.z; q0.w += eg.x*hs.w;
        q1.x += eg.y*hs.x; q1.y += eg.y*hs.y; q1.z += eg.y*hs.z; q1.w += eg.y*hs.w;
        q2.x += eg.z*hs.x; q2.y += eg.z*hs.y; q2.z += eg.z*hs.z; q2.w += eg.z*hs.w;
    }

    float sP = 0.f, s0 = 0.f, s1 = 0.f, s2 = 0.f;
    if (deg > 0) {
        sP = 1.f / (3.f * za); s0 = 1.f / (3.f * z0);
        s1 = 1.f / (3.f * z1); s2 = 1.f / (3.f * z2);
    }
    float* base = g_acc + (size_t)n * 512;
    *(float4*)(base + lane * 4)       = make_float4(aP.x*sP, aP.y*sP, aP.z*sP, aP.w*sP);
    *(float4*)(base + 128 + lane * 4) = make_float4(q0.x*s0, q0.y*s0, q0.z*s0, q0.w*s0);
    *(float4*)(base + 256 + lane * 4) = make_float4(q1.x*s1, q1.y*s1, q1.z*s1, q1.w*s1);
    *(float4*)(base + 384 + lane * 4) = make_float4(q2.x*s2, q2.y*s2, q2.z*s2, q2.w*s2);
    if (lane == 0) g_za[n] = (deg > 0) ? za : 0.f;
}

// ---------------- kernel D: finalize per node (tf32 mma, weights hi/lo) ----------------
#define FW_STRIDE 132
#define SMEM_FIN  ((16896 + 8448) * 4)

__global__ void __launch_bounds__(256, 2) k_final(const float* __restrict__ nf,
                                                  const float* __restrict__ outb,
                                                  const float* __restrict__ gW,
                                                  const float* __restrict__ gb,
                                                  float* __restrict__ out)
{
    extern __shared__ float sm[];
    float* WsT = sm;
    float* As  = sm + 16896;

    int tid = threadIdx.x;
    int w = tid >> 5, lane = tid & 31;
    int g = lane >> 2, tig = lane & 3;
    int nbase = blockIdx.x * NB;

    float c[8][4];
    #pragma unroll
    for (int i = 0; i < 8; i++) { c[i][0]=0.f; c[i][1]=0.f; c[i][2]=0.f; c[i][3]=0.f; }

    for (int ph = 0; ph < 4; ph++) {
        __syncthreads();
        for (int q = tid; q < 2048; q += 256) {
            int nn = q >> 5, kq = q & 31;
            int gn = nbase + nn;
            float4 v = make_float4(0.f,0.f,0.f,0.f);
            if (gn < NN) v = *(const float4*)&g_acc[(size_t)gn * 512 + ph * 128 + kq * 4];
            v.x = tf32f(v.x); v.y = tf32f(v.y); v.z = tf32f(v.z); v.w = tf32f(v.w);
            *(float4*)&As[nn * FW_STRIDE + kq * 4] = v;
        }
        #pragma unroll
        for (int pass = 0; pass < 2; pass++) {
            __syncthreads();
            const float* Csrc = (pass ? g_Ct_lo : g_Ct_hi) + ph * 16384;
            for (int q = tid; q < 4096; q += 256) {
                int rr = q >> 5, kq = q & 31;
                *(float4*)&WsT[rr * FW_STRIDE + kq * 4] = *(const float4*)&Csrc[rr * 128 + kq * 4];
            }
            __syncthreads();
            uint32_t a0[16], a1[16], a2[16], a3[16];
            const float* w0 = &WsT[(w * 16 + g) * FW_STRIDE];
            const float* w1 = &WsT[(w * 16 + 8 + g) * FW_STRIDE];
            #pragma unroll
            for (int kk = 0; kk < 16; kk++) {
                a0[kk] = __float_as_uint(w0[kk * 8 + tig]);
                a2[kk] = __float_as_uint(w0[kk * 8 + tig + 4]);
                a1[kk] = __float_as_uint(w1[kk * 8 + tig]);
                a3[kk] = __float_as_uint(w1[kk * 8 + tig + 4]);
            }
            #pragma unroll
            for (int nt = 0; nt < 8; nt++) {
                const float* bp = &As[(nt * 8 + g) * FW_STRIDE];
                #pragma unroll
                for (int kk = 0; kk < 16; kk++) {
                    uint32_t b0 = __float_as_uint(bp[kk * 8 + tig]);
                    uint32_t b1 = __float_as_uint(bp[kk * 8 + tig + 4]);
                    mma_tf32(c[nt][0], c[nt][1], c[nt][2], c[nt][3],
                             a0[kk], a1[kk], a2[kk], a3[kk], b0, b1);
                }
            }
        }
    }

    __syncthreads();
    #pragma unroll
    for (int nt = 0; nt < 8; nt++) {
        int n0 = nt * 8 + tig * 2;
        As[n0 * FW_STRIDE + w * 16 + g]           = c[nt][0];
        As[(n0 + 1) * FW_STRIDE + w * 16 + g]     = c[nt][1];
        As[n0 * FW_STRIDE + w * 16 + 8 + g]       = c[nt][2];
        As[(n0 + 1) * FW_STRIDE + w * 16 + 8 + g] = c[nt][3];
    }
    __syncthreads();

    float4 b4  = *(const float4*)&outb[lane * 4];
    float4 gw4 = *(const float4*)&gW[lane * 4];
    float gb0 = __ldg(gb);
    #pragma unroll
    for (int t = 0; t < 8; t++) {
        int i = w * 8 + t;
        int n = nbase + i;
        if (n >= NN) break;
        float4 vv = *(const float4*)&As[i * FW_STRIDE + lane * 4];
        bool ok = (g_za[n] > 0.f);
        float4 pre = make_float4(fmaxf(vv.x + b4.x, 0.f), fmaxf(vv.y + b4.y, 0.f),
                                 fmaxf(vv.z + b4.z, 0.f), fmaxf(vv.w + b4.w, 0.f));
        float4 hv  = *(const float4*)&g_h[(size_t)n * DD + lane * 4];
        float4 ho  = ok ? pre : hv;
        float4 nfv = *(const float4*)&nf[(size_t)n * DD + lane * 4];
        float gp = nfv.x * gw4.x + nfv.y * gw4.y + nfv.z * gw4.z + nfv.w * gw4.w;
        #pragma unroll
        for (int o = 16; o; o >>= 1) gp += __shfl_xor_sync(0xffffffffu, gp, o);
        float gate = sigmoidf_(gp + gb0);
        float4 oo = make_float4(gate * ho.x + (1.f - gate) * nfv.x,
                                gate * ho.y + (1.f - gate) * nfv.y,
                                gate * ho.z + (1.f - gate) * nfv.z,
                                gate * ho.w + (1.f - gate) * nfv.w);
        *(float4*)&out[(size_t)n * DD + lane * 4] = oo;
    }
}

// ---------------- launcher ----------------
extern "C" void kernel_launch(void* const* d_in, const int* in_sizes, int n_in,
                              void* d_out, int out_size)
{
    const float* nf   = (const float*)d_in[0];
    const float* ef   = (const float*)d_in[1];
    const int*   src  = (const int*)  d_in[2];
    const int*   dst  = (const int*)  d_in[3];
    const float* natt = (const float*)d_in[4];
    const float* relW = (const float*)d_in[5];
    const float* W1   = (const float*)d_in[6];
    const float* b1   = (const float*)d_in[7];
    const float* W2   = (const float*)d_in[8];
    const float* b2   = (const float*)d_in[9];
    const float* nfcW = (const float*)d_in[10];
    const float* nfcb = (const float*)d_in[11];
    const float* efcW = (const float*)d_in[12];
    const float* efcb = (const float*)d_in[13];
    const float* outW = (const float*)d_in[14];
    const float* outb = (const float*)d_in[15];
    const float* gW   = (const float*)d_in[16];
    const float* gb   = (const float*)d_in[17];
    float* out = (float*)d_out;

    void* pDeg;
    cudaGetSymbolAddress(&pDeg, g_deg);
    cudaMemsetAsync(pDeg, 0, NN * sizeof(int));

    cudaFuncSetAttribute(k_node_fc, cudaFuncAttributeMaxDynamicSharedMemorySize, SMEM_NFC);
    cudaFuncSetAttribute(k_mlp,     cudaFuncAttributeMaxDynamicSharedMemorySize, SMEM_MLP);
    cudaFuncSetAttribute(k_final,   cudaFuncAttributeMaxDynamicSharedMemorySize, SMEM_FIN);

    k_prepW<<<128, 128>>>(nfcW);
    k_node_fc<<<(NN + 127) / 128, 256, SMEM_NFC>>>(nf, nfcb);
    k_combine<<<512, 128>>>(natt, relW, outW);
    k_prepF<<<384, 64>>>(efcW, efcb, W1, b1);
    k_hist<<<(EE + 255) / 256, 256>>>(dst);
    k_scan<<<1, 1024>>>();
    k_fill<<<(EE + 255) / 256, 256>>>(src, dst);
    k_mlp<<<GRID_MLP, 768, SMEM_MLP>>>(ef, W2, b2);
    k_gather<<<(NN + 7) / 8, 256>>>();
    k_final<<<(NN + NB - 1) / NB, 256, SMEM_FIN>>>(nf, outb, gW, gb, out);
}

// round 7
// speedup vs baseline: 3.3335x; 1.0398x over previous
#include <cuda_runtime.h>
#include <cuda_bf16.h>
#include <math.h>
#include <stdint.h>

#define NN   20000
#define NNP  20032
#define EE   320000
#define DD   128
#define DEH  64
#define NTILES (EE / 128)   // 2500
#define GRID_MLP 148
#define NB   64             // nodes per k_final CTA

// ---------------- scratch (device globals; no allocation allowed) ----------------
__device__ float g_h[NN * DD];                 // node_fc output h
__device__ float g_acc[(size_t)NNP * 512];     // per-node [P | Q0 | Q1 | Q2] (pre-scaled)
__device__ float g_za[NNP];                    // sum exp(a) per dst (mask)
__device__ float g_Ct_hi[4 * DD * DD];         // folded C, transposed [ph][out][k], tf32 hi
__device__ float g_Ct_lo[4 * DD * DD];         // tf32 lo residual
__device__ float g_Wt_hi[DD * DD];             // node_fc W transposed [out][k], tf32 hi
__device__ float g_Wt_lo[DD * DD];             // tf32 lo residual
__device__ float g_eg4f[EE * 4];               // exp(sigmoid(g)) per edge, [e][m]
__device__ float g_B[384 * 64];                // folded MLP weights Gᵀ (tf32-rounded fp32)
__device__ float g_bb[384];                    // folded bias bb1
__device__ int   g_deg[NN];
__device__ int   g_off[NN];
__device__ int   g_cur[NN];
__device__ int2  g_epack[EE];                  // (src, e) sorted by dst

__device__ __forceinline__ float sigmoidf_(float x) { return 1.f / (1.f + __expf(-x)); }

__device__ __forceinline__ uint32_t smem_to_u32(const void* p) {
    uint32_t a;
    asm("{ .reg .u64 t; cvta.to.shared.u64 t, %1; cvt.u32.u64 %0, t; }" : "=r"(a) : "l"(p));
    return a;
}
__device__ __forceinline__ uint32_t tf32_rna(float x) {
    uint32_t r; asm("cvt.rna.tf32.f32 %0, %1;" : "=r"(r) : "f"(x)); return r;
}
__device__ __forceinline__ float tf32f(float x) { return __uint_as_float(tf32_rna(x)); }
__device__ __forceinline__ void mma_tf32(float& c0, float& c1, float& c2, float& c3,
                                         uint32_t a0, uint32_t a1, uint32_t a2, uint32_t a3,
                                         uint32_t b0, uint32_t b1) {
    asm volatile("mma.sync.aligned.m16n8k8.row.col.f32.tf32.tf32.f32 "
                 "{%0,%1,%2,%3}, {%4,%5,%6,%7}, {%8,%9}, {%0,%1,%2,%3};"
                 : "+f"(c0), "+f"(c1), "+f"(c2), "+f"(c3)
                 : "r"(a0), "r"(a1), "r"(a2), "r"(a3), "r"(b0), "r"(b1));
}
__device__ __forceinline__ void cp16(float* dst_smem, const float* src) {
    uint32_t d = smem_to_u32(dst_smem);
    asm volatile("cp.async.ca.shared.global [%0], [%1], 16;" :: "r"(d), "l"(src));
}
#define CP_COMMIT asm volatile("cp.async.commit_group;" ::: "memory")
#define CP_WAIT1  asm volatile("cp.async.wait_group 1;"  ::: "memory")

// ---------------- fused prep: prepW | combine | prepF ----------------
__global__ void __launch_bounds__(128) k_prep(const float* __restrict__ natt,
                                              const float* __restrict__ relW,
                                              const float* __restrict__ outW,
                                              const float* __restrict__ nfcW,
                                              const float* __restrict__ efcW,
                                              const float* __restrict__ efcb,
                                              const float* __restrict__ W1,
                                              const float* __restrict__ b1)
{
    __shared__ float shmem[4096];
    int b = blockIdx.x;
    int tid = threadIdx.x;

    if (b < 128) {
        // node_fc weight transpose + tf32 hi/lo split
        int k = b, c = tid;
        float v = nfcW[k * DD + c];
        float hi = tf32f(v);
        g_Wt_hi[c * DD + k] = hi;
        g_Wt_lo[c * DD + k] = tf32f(v - hi);
    } else if (b < 640) {
        // fold C0 = Wsum@U_top, Cm = W_m@U_bot (transposed hi/lo)
        float* row = shmem;
        int bb = b - 128;
        int i = bb >> 7;          // phase 0..3
        int d = bb & 127;         // k
        int c = tid;              // output
        if (i == 0)
            row[c] = natt[d * DD + c] + natt[DD * DD + d * DD + c] + natt[2 * DD * DD + d * DD + c];
        else
            row[c] = relW[(i - 1) * DD * DD + d * DD + c];
        __syncthreads();
        const float* U = (i == 0) ? outW : outW + DD * DD;
        float acc = 0.f;
        #pragma unroll 8
        for (int f = 0; f < DD; f++) acc += row[f] * U[f * DD + c];
        float hi = tf32f(acc);
        g_Ct_hi[i * DD * DD + c * DD + d] = hi;
        g_Ct_lo[i * DD * DD + c * DD + d] = tf32f(acc - hi);
    } else {
        // fold G = efcW @ W1 (tf32) + bias; block handles 2 n's
        float* sW = shmem;   // transposed efcW: sW[fp*64 + k]
        for (int i = tid; i < 4096; i += 128) {
            int k = i >> 6, fp = i & 63;
            sW[fp * 64 + k] = efcW[i];
        }
        __syncthreads();
        int half = tid >> 6;
        int k = tid & 63;
        int n = (b - 640) * 2 + half;
        int m = n >> 7, f = n & 127;
        float acc = 0.f;
        float bacc = b1[n];
        #pragma unroll 4
        for (int fp = 0; fp < DEH; fp++) {
            float w1v = __ldg(&W1[(m * DEH + fp) * DD + f]);
            acc += sW[fp * 64 + k] * w1v;
            bacc += __ldg(&efcb[fp]) * w1v;
        }
        g_B[n * 64 + k] = tf32f(acc);
        if (k == 0) g_bb[n] = bacc;
    }
}

// ---------------- kernel A: h = nf @ node_fc_W + b  (tf32 mma, 3-pass compensated) ----------------
#define NF_STRIDE 132
#define SMEM_NFC ((16896 * 2 + 128) * 4)

__global__ void __launch_bounds__(256, 1) k_node_fc(const float* __restrict__ nf,
                                                    const float* __restrict__ b)
{
    extern __shared__ float sm[];
    float* Ws  = sm;
    float* As  = sm + 16896;
    float* bsm = sm + 2 * 16896;

    int tid = threadIdx.x;
    int w = tid >> 5, lane = tid & 31;
    int g = lane >> 2, tig = lane & 3;
    int nbase = blockIdx.x * 128;
    if (tid < 128) bsm[tid] = b[tid];

    float c[16][4];
    #pragma unroll
    for (int i = 0; i < 16; i++) { c[i][0]=0.f; c[i][1]=0.f; c[i][2]=0.f; c[i][3]=0.f; }

    #pragma unroll
    for (int pass = 0; pass < 3; pass++) {
        __syncthreads();
        if (pass != 1) {
            bool lo = (pass == 2);
            for (int q = tid; q < 4096; q += 256) {
                int n = q >> 5, kq = q & 31;
                int gn = nbase + n;
                float4 v = make_float4(0.f,0.f,0.f,0.f);
                if (gn < NN) v = *(const float4*)&nf[(size_t)gn * DD + kq * 4];
                float4 o;
                if (!lo) o = make_float4(tf32f(v.x), tf32f(v.y), tf32f(v.z), tf32f(v.w));
                else     o = make_float4(tf32f(v.x - tf32f(v.x)), tf32f(v.y - tf32f(v.y)),
                                         tf32f(v.z - tf32f(v.z)), tf32f(v.w - tf32f(v.w)));
                *(float4*)&As[n * NF_STRIDE + kq * 4] = o;
            }
        }
        const float* Wsrc = (pass == 1) ? g_Wt_lo : g_Wt_hi;
        for (int q = tid; q < 4096; q += 256) {
            int rr = q >> 5, kq = q & 31;
            *(float4*)&Ws[rr * NF_STRIDE + kq * 4] = *(const float4*)&Wsrc[rr * DD + kq * 4];
        }
        __syncthreads();

        uint32_t a0[16], a1[16], a2[16], a3[16];
        const float* w0 = &Ws[(w * 16 + g) * NF_STRIDE];
        const float* w1 = &Ws[(w * 16 + 8 + g) * NF_STRIDE];
        #pragma unroll
        for (int kk = 0; kk < 16; kk++) {
            a0[kk] = __float_as_uint(w0[kk * 8 + tig]);
            a2[kk] = __float_as_uint(w0[kk * 8 + tig + 4]);
            a1[kk] = __float_as_uint(w1[kk * 8 + tig]);
            a3[kk] = __float_as_uint(w1[kk * 8 + tig + 4]);
        }
        #pragma unroll
        for (int nt = 0; nt < 16; nt++) {
            const float* bp = &As[(nt * 8 + g) * NF_STRIDE];
            #pragma unroll
            for (int kk = 0; kk < 16; kk++) {
                uint32_t b0 = __float_as_uint(bp[kk * 8 + tig]);
                uint32_t b1 = __float_as_uint(bp[kk * 8 + tig + 4]);
                mma_tf32(c[nt][0], c[nt][1], c[nt][2], c[nt][3],
                         a0[kk], a1[kk], a2[kk], a3[kk], b0, b1);
            }
        }
    }

    __syncthreads();
    #pragma unroll
    for (int nt = 0; nt < 16; nt++) {
        int n0 = nt * 8 + tig * 2;
        As[n0 * NF_STRIDE + w * 16 + g]           = c[nt][0];
        As[(n0 + 1) * NF_STRIDE + w * 16 + g]     = c[nt][1];
        As[n0 * NF_STRIDE + w * 16 + 8 + g]       = c[nt][2];
        As[(n0 + 1) * NF_STRIDE + w * 16 + 8 + g] = c[nt][3];
    }
    __syncthreads();
    for (int q = tid; q < 4096; q += 256) {
        int n = q >> 5, kq = q & 31;
        int gn = nbase + n;
        if (gn < NN) {
            float4 v = *(const float4*)&As[n * NF_STRIDE + kq * 4];
            float4 bb = *(const float4*)&bsm[kq * 4];
            *(float4*)&g_h[(size_t)gn * DD + kq * 4] =
                make_float4(v.x + bb.x, v.y + bb.y, v.z + bb.z, v.w + bb.w);
        }
    }
}

// ---------------- CSR build ----------------
__global__ void k_hist(const int* __restrict__ dst)
{
    int e = blockIdx.x * 256 + threadIdx.x;
    if (e < EE) atomicAdd(&g_deg[dst[e]], 1);
}

__global__ void __launch_bounds__(1024) k_scan()
{
    int tid = threadIdx.x;
    int lane = tid & 31, w = tid >> 5;
    int base = tid * 20;
    int loc[20]; int s = 0;
    #pragma unroll
    for (int j = 0; j < 20; j++) {
        int n = base + j;
        int d = (n < NN) ? g_deg[n] : 0;
        loc[j] = s; s += d;
    }
    int v = s;
    #pragma unroll
    for (int off = 1; off < 32; off <<= 1) {
        int u = __shfl_up_sync(0xffffffffu, v, off);
        if (lane >= off) v += u;
    }
    __shared__ int wsum[32];
    if (lane == 31) wsum[w] = v;
    __syncthreads();
    if (w == 0) {
        int t = wsum[lane];
        #pragma unroll
        for (int off = 1; off < 32; off <<= 1) {
            int u = __shfl_up_sync(0xffffffffu, t, off);
            if (lane >= off) t += u;
        }
        wsum[lane] = t;
    }
    __syncthreads();
    int excl = v - s + (w > 0 ? wsum[w - 1] : 0);
    #pragma unroll
    for (int j = 0; j < 20; j++) {
        int n = base + j;
        if (n < NN) { int o = excl + loc[j]; g_off[n] = o; g_cur[n] = o; }
    }
}

__global__ void k_fill(const int* __restrict__ src, const int* __restrict__ dst)
{
    int e = blockIdx.x * 256 + threadIdx.x;
    if (e < EE) {
        int d = dst[e];
        int pos = atomicAdd(&g_cur[d], 1);
        g_epack[pos] = make_int2(src[e], e);
    }
}

// ---------------- kernel B: tensor-core (mma.sync tf32) edge MLP -> g_eg4f ----------------
#define BP_STRIDE 72
#define A_STRIDE  68
#define A_BUF_F   (128 * A_STRIDE)          // 8704 floats
#define OFF_EPI   27648
#define OFF_A     (27648 + 768)
#define SMEM_MLP  ((27648 + 768 + 2 * A_BUF_F) * 4)

__global__ void __launch_bounds__(768, 1) k_mlp(const float* __restrict__ ef,
                                                const float* __restrict__ W2,
                                                const float* __restrict__ b2)
{
    extern __shared__ float sm[];
    float*  Bp  = sm;
    float2* epi = (float2*)(sm + OFF_EPI);
    float*  As  = sm + OFF_A;

    int tid = threadIdx.x;
    int wid = tid >> 5, lane = tid & 31;
    int g = lane >> 2, tig = lane & 3;
    int m = wid >> 3;          // head 0..2
    int r = wid & 7;           // row slice 0..7
    int rowbase = r * 16;

    for (int i = tid; i < 384 * 64; i += 768) {
        int n = i >> 6, k = i & 63;
        int kk = k >> 3, t = k & 7;
        int pos = (t < 4) ? (n * BP_STRIDE + kk * 8 + t * 2)
                          : (n * BP_STRIDE + kk * 8 + (t - 4) * 2 + 1);
        Bp[pos] = g_B[i];
    }
    if (tid < 384) epi[tid] = make_float2(g_bb[tid], __ldg(W2 + tid));
    __syncthreads();

    float b2m = __ldg(b2 + m);

    int t0 = blockIdx.x;
    {
        const float* srcb = ef + (size_t)t0 * 8192;
        for (int c = tid; c < 2048; c += 768)
            cp16(As + (c >> 4) * A_STRIDE + (c & 15) * 4, srcb + c * 4);
    }
    CP_COMMIT;

    int buf = 0;
    for (int t = t0; t < NTILES; t += GRID_MLP) {
        int tn = t + GRID_MLP;
        if (tn < NTILES) {
            const float* srcb = ef + (size_t)tn * 8192;
            float* dstb = As + (buf ^ 1) * A_BUF_F;
            for (int c = tid; c < 2048; c += 768)
                cp16(dstb + (c >> 4) * A_STRIDE + (c & 15) * 4, srcb + c * 4);
        }
        CP_COMMIT;
        CP_WAIT1;
        __syncthreads();

        const float* A = As + buf * A_BUF_F;
        const float* r0p = A + (rowbase + g) * A_STRIDE;
        const float* r1p = A + (rowbase + g + 8) * A_STRIDE;
        uint32_t a0[8], a1[8], a2[8], a3[8];
        #pragma unroll
        for (int kk = 0; kk < 8; kk++) {
            a0[kk] = tf32_rna(r0p[kk * 8 + tig]);
            a2[kk] = tf32_rna(r0p[kk * 8 + tig + 4]);
            a1[kk] = tf32_rna(r1p[kk * 8 + tig]);
            a3[kk] = tf32_rna(r1p[kk * 8 + tig + 4]);
        }

        float p0 = 0.f, p1 = 0.f;
        #pragma unroll 4
        for (int nt = 0; nt < 16; nt++) {
            int n0 = m * 128 + nt * 8;
            float c0 = 0.f, c1 = 0.f, c2 = 0.f, c3 = 0.f;
            const float2* bp = (const float2*)(Bp + (n0 + g) * BP_STRIDE) + tig;
            #pragma unroll
            for (int kk = 0; kk < 8; kk++) {
                float2 bv = bp[kk * 4];
                uint32_t b0 = __float_as_uint(bv.x);
                uint32_t b1 = __float_as_uint(bv.y);
                mma_tf32(c0, c1, c2, c3, a0[kk], a1[kk], a2[kk], a3[kk], b0, b1);
            }
            float2 e0 = epi[n0 + 2 * tig];
            float2 e1 = epi[n0 + 2 * tig + 1];
            p0 += fmaxf(c0 + e0.x, 0.f) * e0.y + fmaxf(c1 + e1.x, 0.f) * e1.y;
            p1 += fmaxf(c2 + e0.x, 0.f) * e0.y + fmaxf(c3 + e1.x, 0.f) * e1.y;
        }
        #pragma unroll
        for (int off = 1; off <= 2; off <<= 1) {
            p0 += __shfl_xor_sync(0xffffffffu, p0, off);
            p1 += __shfl_xor_sync(0xffffffffu, p1, off);
        }
        if (tig == 0) {
            int e = t * 128 + rowbase + g;
            g_eg4f[(e)     * 4 + m] = __expf(sigmoidf_(p0 + b2m));
            g_eg4f[(e + 8) * 4 + m] = __expf(sigmoidf_(p1 + b2m));
        }
        __syncthreads();
        buf ^= 1;
    }
}

// ---------------- kernel C: gather (warp per dst node, no atomics, unroll 4) ----------------
__global__ void __launch_bounds__(256) k_gather()
{
    int n = (blockIdx.x * 256 + threadIdx.x) >> 5;
    int lane = threadIdx.x & 31;
    if (n >= NN) return;

    int off = g_off[n];
    int deg = g_deg[n];
    float4 hd = *(const float4*)&g_h[(size_t)n * DD + lane * 4];

    float4 aP = make_float4(0.f,0.f,0.f,0.f), q0 = aP, q1 = aP, q2 = aP;
    float za = 0.f, z0 = 0.f, z1 = 0.f, z2 = 0.f;

    int j = 0;
    for (; j + 3 < deg; j += 4) {
        float4 hs[4], eg[4]; float p[4];
        #pragma unroll
        for (int u = 0; u < 4; u++) {
            int2 se = __ldg(&g_epack[off + j + u]);
            hs[u] = *(const float4*)&g_h[(size_t)se.x * DD + lane * 4];
            eg[u] = *(const float4*)&g_eg4f[(size_t)se.y * 4];
            p[u] = hs[u].x*hd.x + hs[u].y*hd.y + hs[u].z*hd.z + hs[u].w*hd.w;
        }
        #pragma unroll
        for (int o = 16; o; o >>= 1) {
            #pragma unroll
            for (int u = 0; u < 4; u++) p[u] += __shfl_xor_sync(0xffffffffu, p[u], o);
        }
        #pragma unroll
        for (int u = 0; u < 4; u++) {
            float ea = __expf(p[u]);
            za += ea; z0 += eg[u].x; z1 += eg[u].y; z2 += eg[u].z;
            aP.x += ea*hs[u].x; aP.y += ea*hs[u].y; aP.z += ea*hs[u].z; aP.w += ea*hs[u].w;
            q0.x += eg[u].x*hs[u].x; q0.y += eg[u].x*hs[u].y; q0.z += eg[u].x*hs[u].z; q0.w += eg[u].x*hs[u].w;
            q1.x += eg[u].y*hs[u].x; q1.y += eg[u].y*hs[u].y; q1.z += eg[u].y*hs[u].z; q1.w += eg[u].y*hs[u].w;
            q2.x += eg[u].z*hs[u].x; q2.y += eg[u].z*hs[u].y; q2.z += eg[u].z*hs[u].z; q2.w += eg[u].z*hs[u].w;
        }
    }
    for (; j < deg; j++) {
        int2 se = __ldg(&g_epack[off + j]);
        float4 hs = *(const float4*)&g_h[(size_t)se.x * DD + lane * 4];
        float4 eg = *(const float4*)&g_eg4f[(size_t)se.y * 4];
        float pa = hs.x*hd.x + hs.y*hd.y + hs.z*hd.z + hs.w*hd.w;
        #pragma unroll
        for (int o = 16; o; o >>= 1) pa += __shfl_xor_sync(0xffffffffu, pa, o);
        float ea = __expf(pa);
        za += ea; z0 += eg.x; z1 += eg.y; z2 += eg.z;
        aP.x += ea*hs.x; aP.y += ea*hs.y; aP.z += ea*hs.z; aP.w += ea*hs.w;
        q0.x += eg.x*hs.x; q0.y += eg.x*hs.y; q0.z += eg.x*hs.z; q0.w += eg.x*hs.w;
        q1.x += eg.y*hs.x; q1.y += eg.y*hs.y; q1.z += eg.y*hs.z; q1.w += eg.y*hs.w;
        q2.x += eg.z*hs.x; q2.y += eg.z*hs.y; q2.z += eg.z*hs.z; q2.w += eg.z*hs.w;
    }

    float sP = 0.f, s0 = 0.f, s1 = 0.f, s2 = 0.f;
    if (deg > 0) {
        sP = 1.f / (3.f * za); s0 = 1.f / (3.f * z0);
        s1 = 1.f / (3.f * z1); s2 = 1.f / (3.f * z2);
    }
    float* base = g_acc + (size_t)n * 512;
    *(float4*)(base + lane * 4)       = make_float4(aP.x*sP, aP.y*sP, aP.z*sP, aP.w*sP);
    *(float4*)(base + 128 + lane * 4) = make_float4(q0.x*s0, q0.y*s0, q0.z*s0, q0.w*s0);
    *(float4*)(base + 256 + lane * 4) = make_float4(q1.x*s1, q1.y*s1, q1.z*s1, q1.w*s1);
    *(float4*)(base + 384 + lane * 4) = make_float4(q2.x*s2, q2.y*s2, q2.z*s2, q2.w*s2);
    if (lane == 0) g_za[n] = (deg > 0) ? za : 0.f;
}

// ---------------- kernel D: finalize per node (tf32 mma, weights hi/lo) ----------------
#define FW_STRIDE 132
#define SMEM_FIN  ((16896 + 8448) * 4)

__global__ void __launch_bounds__(256, 2) k_final(const float* __restrict__ nf,
                                                  const float* __restrict__ outb,
                                                  const float* __restrict__ gW,
                                                  const float* __restrict__ gb,
                                                  float* __restrict__ out)
{
    extern __shared__ float sm[];
    float* WsT = sm;
    float* As  = sm + 16896;

    int tid = threadIdx.x;
    int w = tid >> 5, lane = tid & 31;
    int g = lane >> 2, tig = lane & 3;
    int nbase = blockIdx.x * NB;

    float c[8][4];
    #pragma unroll
    for (int i = 0; i < 8; i++) { c[i][0]=0.f; c[i][1]=0.f; c[i][2]=0.f; c[i][3]=0.f; }

    for (int ph = 0; ph < 4; ph++) {
        __syncthreads();
        for (int q = tid; q < 2048; q += 256) {
            int nn = q >> 5, kq = q & 31;
            int gn = nbase + nn;
            float4 v = make_float4(0.f,0.f,0.f,0.f);
            if (gn < NN) v = *(const float4*)&g_acc[(size_t)gn * 512 + ph * 128 + kq * 4];
            v.x = tf32f(v.x); v.y = tf32f(v.y); v.z = tf32f(v.z); v.w = tf32f(v.w);
            *(float4*)&As[nn * FW_STRIDE + kq * 4] = v;
        }
        #pragma unroll
        for (int pass = 0; pass < 2; pass++) {
            __syncthreads();
            const float* Csrc = (pass ? g_Ct_lo : g_Ct_hi) + ph * 16384;
            for (int q = tid; q < 4096; q += 256) {
                int rr = q >> 5, kq = q & 31;
                *(float4*)&WsT[rr * FW_STRIDE + kq * 4] = *(const float4*)&Csrc[rr * 128 + kq * 4];
            }
            __syncthreads();
            uint32_t a0[16], a1[16], a2[16], a3[16];
            const float* w0 = &WsT[(w * 16 + g) * FW_STRIDE];
            const float* w1 = &WsT[(w * 16 + 8 + g) * FW_STRIDE];
            #pragma unroll
            for (int kk = 0; kk < 16; kk++) {
                a0[kk] = __float_as_uint(w0[kk * 8 + tig]);
                a2[kk] = __float_as_uint(w0[kk * 8 + tig + 4]);
                a1[kk] = __float_as_uint(w1[kk * 8 + tig]);
                a3[kk] = __float_as_uint(w1[kk * 8 + tig + 4]);
            }
            #pragma unroll
            for (int nt = 0; nt < 8; nt++) {
                const float* bp = &As[(nt * 8 + g) * FW_STRIDE];
                #pragma unroll
                for (int kk = 0; kk < 16; kk++) {
                    uint32_t b0 = __float_as_uint(bp[kk * 8 + tig]);
                    uint32_t b1 = __float_as_uint(bp[kk * 8 + tig + 4]);
                    mma_tf32(c[nt][0], c[nt][1], c[nt][2], c[nt][3],
                             a0[kk], a1[kk], a2[kk], a3[kk], b0, b1);
                }
            }
        }
    }

    __syncthreads();
    #pragma unroll
    for (int nt = 0; nt < 8; nt++) {
        int n0 = nt * 8 + tig * 2;
        As[n0 * FW_STRIDE + w * 16 + g]           = c[nt][0];
        As[(n0 + 1) * FW_STRIDE + w * 16 + g]     = c[nt][1];
        As[n0 * FW_STRIDE + w * 16 + 8 + g]       = c[nt][2];
        As[(n0 + 1) * FW_STRIDE + w * 16 + 8 + g] = c[nt][3];
    }
    __syncthreads();

    float4 b4  = *(const float4*)&outb[lane * 4];
    float4 gw4 = *(const float4*)&gW[lane * 4];
    float gb0 = __ldg(gb);
    #pragma unroll
    for (int t = 0; t < 8; t++) {
        int i = w * 8 + t;
        int n = nbase + i;
        if (n >= NN) break;
        float4 vv = *(const float4*)&As[i * FW_STRIDE + lane * 4];
        bool ok = (g_za[n] > 0.f);
        float4 pre = make_float4(fmaxf(vv.x + b4.x, 0.f), fmaxf(vv.y + b4.y, 0.f),
                                 fmaxf(vv.z + b4.z, 0.f), fmaxf(vv.w + b4.w, 0.f));
        float4 hv  = *(const float4*)&g_h[(size_t)n * DD + lane * 4];
        float4 ho  = ok ? pre : hv;
        float4 nfv = *(const float4*)&nf[(size_t)n * DD + lane * 4];
        float gp = nfv.x * gw4.x + nfv.y * gw4.y + nfv.z * gw4.z + nfv.w * gw4.w;
        #pragma unroll
        for (int o = 16; o; o >>= 1) gp += __shfl_xor_sync(0xffffffffu, gp, o);
        float gate = sigmoidf_(gp + gb0);
        float4 oo = make_float4(gate * ho.x + (1.f - gate) * nfv.x,
                                gate * ho.y + (1.f - gate) * nfv.y,
                                gate * ho.z + (1.f - gate) * nfv.z,
                                gate * ho.w + (1.f - gate) * nfv.w);
        *(float4*)&out[(size_t)n * DD + lane * 4] = oo;
    }
}

// ---------------- launcher ----------------
extern "C" void kernel_launch(void* const* d_in, const int* in_sizes, int n_in,
                              void* d_out, int out_size)
{
    const float* nf   = (const float*)d_in[0];
    const float* ef   = (const float*)d_in[1];
    const int*   src  = (const int*)  d_in[2];
    const int*   dst  = (const int*)  d_in[3];
    const float* natt = (const float*)d_in[4];
    const float* relW = (const float*)d_in[5];
    const float* W1   = (const float*)d_in[6];
    const float* b1   = (const float*)d_in[7];
    const float* W2   = (const float*)d_in[8];
    const float* b2   = (const float*)d_in[9];
    const float* nfcW = (const float*)d_in[10];
    const float* nfcb = (const float*)d_in[11];
    const float* efcW = (const float*)d_in[12];
    const float* efcb = (const float*)d_in[13];
    const float* outW = (const float*)d_in[14];
    const float* outb = (const float*)d_in[15];
    const float* gW   = (const float*)d_in[16];
    const float* gb   = (const float*)d_in[17];
    float* out = (float*)d_out;

    // one-time host resources (created outside capture; work per call is identical)
    static cudaStream_t s_side = nullptr;
    static cudaEvent_t e_fork = nullptr, e_join = nullptr;
    if (s_side == nullptr) {
        cudaStreamCreateWithFlags(&s_side, cudaStreamNonBlocking);
        cudaEventCreateWithFlags(&e_fork, cudaEventDisableTiming);
        cudaEventCreateWithFlags(&e_join, cudaEventDisableTiming);
    }

    void* pDeg;
    cudaGetSymbolAddress(&pDeg, g_deg);

    cudaFuncSetAttribute(k_node_fc, cudaFuncAttributeMaxDynamicSharedMemorySize, SMEM_NFC);
    cudaFuncSetAttribute(k_mlp,     cudaFuncAttributeMaxDynamicSharedMemorySize, SMEM_MLP);
    cudaFuncSetAttribute(k_final,   cudaFuncAttributeMaxDynamicSharedMemorySize, SMEM_FIN);

    // fork: CSR build on side stream (independent of compute chain)
    cudaEventRecord(e_fork, 0);
    cudaStreamWaitEvent(s_side, e_fork, 0);
    cudaMemsetAsync(pDeg, 0, NN * sizeof(int), s_side);
    k_hist<<<(EE + 255) / 256, 256, 0, s_side>>>(dst);
    k_scan<<<1, 1024, 0, s_side>>>();
    k_fill<<<(EE + 255) / 256, 256, 0, s_side>>>(src, dst);
    cudaEventRecord(e_join, s_side);

    // main chain
    k_prep<<<832, 128>>>(natt, relW, outW, nfcW, efcW, efcb, W1, b1);
    k_node_fc<<<(NN + 127) / 128, 256, SMEM_NFC>>>(nf, nfcb);
    k_mlp<<<GRID_MLP, 768, SMEM_MLP>>>(ef, W2, b2);

    // join, then reduction + finalize
    cudaStreamWaitEvent(0, e_join, 0);
    k_gather<<<(NN + 7) / 8, 256>>>();
    k_final<<<(NN + NB - 1) / NB, 256, SMEM_FIN>>>(nf, outb, gW, gb, out);
}

// round 8
// speedup vs baseline: 3.3390x; 1.0017x over previous
#include <cuda_runtime.h>
#include <cuda_bf16.h>
#include <math.h>
#include <stdint.h>

#define NN   20000
#define NNP  20032
#define EE   320000
#define DD   128
#define DEH  64
#define NTILES (EE / 128)   // 2500
#define GRID_MLP 148
#define NB   64             // nodes per k_final CTA

// ---------------- scratch (device globals; no allocation allowed) ----------------
__device__ float g_h[NN * DD];                 // node_fc output h
__device__ float g_acc[(size_t)NNP * 512];     // per-node [P | Q0 | Q1 | Q2] (pre-scaled)
__device__ float g_za[NNP];                    // sum exp(a) per dst (mask)
__device__ float g_Ct_hi[4 * DD * DD];         // folded C, transposed [ph][out][k], tf32 hi
__device__ float g_Ct_lo[4 * DD * DD];         // tf32 lo residual
__device__ float g_Wt_hi[DD * DD];             // node_fc W transposed [out][k], tf32 hi
__device__ float g_Wt_lo[DD * DD];             // tf32 lo residual
__device__ float g_eg4f[EE * 4];               // exp(sigmoid(g)) per edge, [e][m]
__device__ float g_B[384 * 64];                // folded MLP weights Gᵀ (tf32-rounded fp32)
__device__ float g_bb[384];                    // folded bias bb1
__device__ int   g_deg[NN];
__device__ int   g_off[NN];
__device__ int   g_cur[NN];
__device__ int2  g_epack[EE];                  // (src, e) sorted by dst

__device__ __forceinline__ float sigmoidf_(float x) { return 1.f / (1.f + __expf(-x)); }

__device__ __forceinline__ uint32_t smem_to_u32(const void* p) {
    uint32_t a;
    asm("{ .reg .u64 t; cvta.to.shared.u64 t, %1; cvt.u32.u64 %0, t; }" : "=r"(a) : "l"(p));
    return a;
}
__device__ __forceinline__ uint32_t tf32_rna(float x) {
    uint32_t r; asm("cvt.rna.tf32.f32 %0, %1;" : "=r"(r) : "f"(x)); return r;
}
__device__ __forceinline__ float tf32f(float x) { return __uint_as_float(tf32_rna(x)); }
__device__ __forceinline__ void mma_tf32(float& c0, float& c1, float& c2, float& c3,
                                         uint32_t a0, uint32_t a1, uint32_t a2, uint32_t a3,
                                         uint32_t b0, uint32_t b1) {
    asm volatile("mma.sync.aligned.m16n8k8.row.col.f32.tf32.tf32.f32 "
                 "{%0,%1,%2,%3}, {%4,%5,%6,%7}, {%8,%9}, {%0,%1,%2,%3};"
                 : "+f"(c0), "+f"(c1), "+f"(c2), "+f"(c3)
                 : "r"(a0), "r"(a1), "r"(a2), "r"(a3), "r"(b0), "r"(b1));
}
__device__ __forceinline__ void cp16(float* dst_smem, const float* src) {
    uint32_t d = smem_to_u32(dst_smem);
    asm volatile("cp.async.ca.shared.global [%0], [%1], 16;" :: "r"(d), "l"(src));
}
#define CP_COMMIT asm volatile("cp.async.commit_group;" ::: "memory")
#define CP_WAIT1  asm volatile("cp.async.wait_group 1;"  ::: "memory")

// ---------------- prep (critical path): prepW | prepF ----------------
__global__ void __launch_bounds__(128) k_prep_early(const float* __restrict__ nfcW,
                                                    const float* __restrict__ efcW,
                                                    const float* __restrict__ efcb,
                                                    const float* __restrict__ W1,
                                                    const float* __restrict__ b1)
{
    __shared__ float shmem[4096];
    int b = blockIdx.x;
    int tid = threadIdx.x;

    if (b < 128) {
        int k = b, c = tid;
        float v = nfcW[k * DD + c];
        float hi = tf32f(v);
        g_Wt_hi[c * DD + k] = hi;
        g_Wt_lo[c * DD + k] = tf32f(v - hi);
    } else {
        // fold G = efcW @ W1 (tf32) + bias; block handles 2 n's
        float* sW = shmem;   // transposed efcW: sW[fp*64 + k]
        for (int i = tid; i < 4096; i += 128) {
            int k = i >> 6, fp = i & 63;
            sW[fp * 64 + k] = efcW[i];
        }
        __syncthreads();
        int half = tid >> 6;
        int k = tid & 63;
        int n = (b - 128) * 2 + half;
        int m = n >> 7, f = n & 127;
        float acc = 0.f;
        float bacc = b1[n];
        #pragma unroll 4
        for (int fp = 0; fp < DEH; fp++) {
            float w1v = __ldg(&W1[(m * DEH + fp) * DD + f]);
            acc += sW[fp * 64 + k] * w1v;
            bacc += __ldg(&efcb[fp]) * w1v;
        }
        g_B[n * 64 + k] = tf32f(acc);
        if (k == 0) g_bb[n] = bacc;
    }
}

// ---------------- combine (side stream): C0 = Wsum@U_top, Cm = W_m@U_bot ----------------
__global__ void __launch_bounds__(128) k_combine(const float* __restrict__ natt,
                                                 const float* __restrict__ relW,
                                                 const float* __restrict__ outW)
{
    __shared__ float row[DD];
    int i = blockIdx.x >> 7;          // phase 0..3
    int d = blockIdx.x & 127;         // k
    int c = threadIdx.x;              // output
    if (i == 0)
        row[c] = natt[d * DD + c] + natt[DD * DD + d * DD + c] + natt[2 * DD * DD + d * DD + c];
    else
        row[c] = relW[(i - 1) * DD * DD + d * DD + c];
    __syncthreads();
    const float* U = (i == 0) ? outW : outW + DD * DD;
    float acc = 0.f;
    #pragma unroll 8
    for (int f = 0; f < DD; f++) acc += row[f] * U[f * DD + c];
    float hi = tf32f(acc);
    g_Ct_hi[i * DD * DD + c * DD + d] = hi;
    g_Ct_lo[i * DD * DD + c * DD + d] = tf32f(acc - hi);
}

// ---------------- kernel A: h = nf @ node_fc_W + b  (tf32 mma, 3-pass compensated) ----------------
#define NF_STRIDE 132
#define SMEM_NFC ((16896 * 2 + 128) * 4)

__global__ void __launch_bounds__(256, 1) k_node_fc(const float* __restrict__ nf,
                                                    const float* __restrict__ b)
{
    extern __shared__ float sm[];
    float* Ws  = sm;
    float* As  = sm + 16896;
    float* bsm = sm + 2 * 16896;

    int tid = threadIdx.x;
    int w = tid >> 5, lane = tid & 31;
    int g = lane >> 2, tig = lane & 3;
    int nbase = blockIdx.x * 128;
    if (tid < 128) bsm[tid] = b[tid];

    float c[16][4];
    #pragma unroll
    for (int i = 0; i < 16; i++) { c[i][0]=0.f; c[i][1]=0.f; c[i][2]=0.f; c[i][3]=0.f; }

    #pragma unroll
    for (int pass = 0; pass < 3; pass++) {
        __syncthreads();
        if (pass != 1) {
            bool lo = (pass == 2);
            for (int q = tid; q < 4096; q += 256) {
                int n = q >> 5, kq = q & 31;
                int gn = nbase + n;
                float4 v = make_float4(0.f,0.f,0.f,0.f);
                if (gn < NN) v = *(const float4*)&nf[(size_t)gn * DD + kq * 4];
                float4 o;
                if (!lo) o = make_float4(tf32f(v.x), tf32f(v.y), tf32f(v.z), tf32f(v.w));
                else     o = make_float4(tf32f(v.x - tf32f(v.x)), tf32f(v.y - tf32f(v.y)),
                                         tf32f(v.z - tf32f(v.z)), tf32f(v.w - tf32f(v.w)));
                *(float4*)&As[n * NF_STRIDE + kq * 4] = o;
            }
        }
        const float* Wsrc = (pass == 1) ? g_Wt_lo : g_Wt_hi;
        for (int q = tid; q < 4096; q += 256) {
            int rr = q >> 5, kq = q & 31;
            *(float4*)&Ws[rr * NF_STRIDE + kq * 4] = *(const float4*)&Wsrc[rr * DD + kq * 4];
        }
        __syncthreads();

        uint32_t a0[16], a1[16], a2[16], a3[16];
        const float* w0 = &Ws[(w * 16 + g) * NF_STRIDE];
        const float* w1 = &Ws[(w * 16 + 8 + g) * NF_STRIDE];
        #pragma unroll
        for (int kk = 0; kk < 16; kk++) {
            a0[kk] = __float_as_uint(w0[kk * 8 + tig]);
            a2[kk] = __float_as_uint(w0[kk * 8 + tig + 4]);
            a1[kk] = __float_as_uint(w1[kk * 8 + tig]);
            a3[kk] = __float_as_uint(w1[kk * 8 + tig + 4]);
        }
        #pragma unroll
        for (int nt = 0; nt < 16; nt++) {
            const float* bp = &As[(nt * 8 + g) * NF_STRIDE];
            #pragma unroll
            for (int kk = 0; kk < 16; kk++) {
                uint32_t b0 = __float_as_uint(bp[kk * 8 + tig]);
                uint32_t b1 = __float_as_uint(bp[kk * 8 + tig + 4]);
                mma_tf32(c[nt][0], c[nt][1], c[nt][2], c[nt][3],
                         a0[kk], a1[kk], a2[kk], a3[kk], b0, b1);
            }
        }
    }

    __syncthreads();
    #pragma unroll
    for (int nt = 0; nt < 16; nt++) {
        int n0 = nt * 8 + tig * 2;
        As[n0 * NF_STRIDE + w * 16 + g]           = c[nt][0];
        As[(n0 + 1) * NF_STRIDE + w * 16 + g]     = c[nt][1];
        As[n0 * NF_STRIDE + w * 16 + 8 + g]       = c[nt][2];
        As[(n0 + 1) * NF_STRIDE + w * 16 + 8 + g] = c[nt][3];
    }
    __syncthreads();
    for (int q = tid; q < 4096; q += 256) {
        int n = q >> 5, kq = q & 31;
        int gn = nbase + n;
        if (gn < NN) {
            float4 v = *(const float4*)&As[n * NF_STRIDE + kq * 4];
            float4 bb = *(const float4*)&bsm[kq * 4];
            *(float4*)&g_h[(size_t)gn * DD + kq * 4] =
                make_float4(v.x + bb.x, v.y + bb.y, v.z + bb.z, v.w + bb.w);
        }
    }
}

// ---------------- CSR build ----------------
__global__ void k_hist(const int* __restrict__ dst)
{
    int e = blockIdx.x * 256 + threadIdx.x;
    if (e < EE) atomicAdd(&g_deg[dst[e]], 1);
}

__global__ void __launch_bounds__(1024) k_scan()
{
    int tid = threadIdx.x;
    int lane = tid & 31, w = tid >> 5;
    int base = tid * 20;
    int loc[20]; int s = 0;
    #pragma unroll
    for (int j = 0; j < 20; j++) {
        int n = base + j;
        int d = (n < NN) ? g_deg[n] : 0;
        loc[j] = s; s += d;
    }
    int v = s;
    #pragma unroll
    for (int off = 1; off < 32; off <<= 1) {
        int u = __shfl_up_sync(0xffffffffu, v, off);
        if (lane >= off) v += u;
    }
    __shared__ int wsum[32];
    if (lane == 31) wsum[w] = v;
    __syncthreads();
    if (w == 0) {
        int t = wsum[lane];
        #pragma unroll
        for (int off = 1; off < 32; off <<= 1) {
            int u = __shfl_up_sync(0xffffffffu, t, off);
            if (lane >= off) t += u;
        }
        wsum[lane] = t;
    }
    __syncthreads();
    int excl = v - s + (w > 0 ? wsum[w - 1] : 0);
    #pragma unroll
    for (int j = 0; j < 20; j++) {
        int n = base + j;
        if (n < NN) { int o = excl + loc[j]; g_off[n] = o; g_cur[n] = o; }
    }
}

__global__ void k_fill(const int* __restrict__ src, const int* __restrict__ dst)
{
    int e = blockIdx.x * 256 + threadIdx.x;
    if (e < EE) {
        int d = dst[e];
        int pos = atomicAdd(&g_cur[d], 1);
        g_epack[pos] = make_int2(src[e], e);
    }
}

// ---------------- kernel B: tensor-core (mma.sync tf32) edge MLP -> g_eg4f ----------------
#define BP_STRIDE 72
#define A_STRIDE  68
#define A_BUF_F   (128 * A_STRIDE)          // 8704 floats
#define OFF_EPI   27648
#define OFF_A     (27648 + 768)
#define SMEM_MLP  ((27648 + 768 + 2 * A_BUF_F) * 4)

__global__ void __launch_bounds__(768, 1) k_mlp(const float* __restrict__ ef,
                                                const float* __restrict__ W2,
                                                const float* __restrict__ b2)
{
    extern __shared__ float sm[];
    float*  Bp  = sm;
    float2* epi = (float2*)(sm + OFF_EPI);
    float*  As  = sm + OFF_A;

    int tid = threadIdx.x;
    int wid = tid >> 5, lane = tid & 31;
    int g = lane >> 2, tig = lane & 3;
    int m = wid >> 3;          // head 0..2
    int r = wid & 7;           // row slice 0..7
    int rowbase = r * 16;

    for (int i = tid; i < 384 * 64; i += 768) {
        int n = i >> 6, k = i & 63;
        int kk = k >> 3, t = k & 7;
        int pos = (t < 4) ? (n * BP_STRIDE + kk * 8 + t * 2)
                          : (n * BP_STRIDE + kk * 8 + (t - 4) * 2 + 1);
        Bp[pos] = g_B[i];
    }
    if (tid < 384) epi[tid] = make_float2(g_bb[tid], __ldg(W2 + tid));
    __syncthreads();

    float b2m = __ldg(b2 + m);

    int t0 = blockIdx.x;
    {
        const float* srcb = ef + (size_t)t0 * 8192;
        for (int c = tid; c < 2048; c += 768)
            cp16(As + (c >> 4) * A_STRIDE + (c & 15) * 4, srcb + c * 4);
    }
    CP_COMMIT;

    int buf = 0;
    for (int t = t0; t < NTILES; t += GRID_MLP) {
        int tn = t + GRID_MLP;
        if (tn < NTILES) {
            const float* srcb = ef + (size_t)tn * 8192;
            float* dstb = As + (buf ^ 1) * A_BUF_F;
            for (int c = tid; c < 2048; c += 768)
                cp16(dstb + (c >> 4) * A_STRIDE + (c & 15) * 4, srcb + c * 4);
        }
        CP_COMMIT;
        CP_WAIT1;
        __syncthreads();

        const float* A = As + buf * A_BUF_F;
        const float* r0p = A + (rowbase + g) * A_STRIDE;
        const float* r1p = A + (rowbase + g + 8) * A_STRIDE;
        uint32_t a0[8], a1[8], a2[8], a3[8];
        #pragma unroll
        for (int kk = 0; kk < 8; kk++) {
            a0[kk] = tf32_rna(r0p[kk * 8 + tig]);
            a2[kk] = tf32_rna(r0p[kk * 8 + tig + 4]);
            a1[kk] = tf32_rna(r1p[kk * 8 + tig]);
            a3[kk] = tf32_rna(r1p[kk * 8 + tig + 4]);
        }

        float p0 = 0.f, p1 = 0.f;
        #pragma unroll 4
        for (int nt = 0; nt < 16; nt++) {
            int n0 = m * 128 + nt * 8;
            float c0 = 0.f, c1 = 0.f, c2 = 0.f, c3 = 0.f;
            const float2* bp = (const float2*)(Bp + (n0 + g) * BP_STRIDE) + tig;
            #pragma unroll
            for (int kk = 0; kk < 8; kk++) {
                float2 bv = bp[kk * 4];
                uint32_t b0 = __float_as_uint(bv.x);
                uint32_t b1 = __float_as_uint(bv.y);
                mma_tf32(c0, c1, c2, c3, a0[kk], a1[kk], a2[kk], a3[kk], b0, b1);
            }
            float2 e0 = epi[n0 + 2 * tig];
            float2 e1 = epi[n0 + 2 * tig + 1];
            p0 += fmaxf(c0 + e0.x, 0.f) * e0.y + fmaxf(c1 + e1.x, 0.f) * e1.y;
            p1 += fmaxf(c2 + e0.x, 0.f) * e0.y + fmaxf(c3 + e1.x, 0.f) * e1.y;
        }
        #pragma unroll
        for (int off = 1; off <= 2; off <<= 1) {
            p0 += __shfl_xor_sync(0xffffffffu, p0, off);
            p1 += __shfl_xor_sync(0xffffffffu, p1, off);
        }
        if (tig == 0) {
            int e = t * 128 + rowbase + g;
            g_eg4f[(e)     * 4 + m] = __expf(sigmoidf_(p0 + b2m));
            g_eg4f[(e + 8) * 4 + m] = __expf(sigmoidf_(p1 + b2m));
        }
        __syncthreads();
        buf ^= 1;
    }
}

// ---------------- kernel C: gather (warp per dst node; batched epack via shfl) ----------------
__global__ void __launch_bounds__(256) k_gather()
{
    int n = (blockIdx.x * 256 + threadIdx.x) >> 5;
    int lane = threadIdx.x & 31;
    if (n >= NN) return;

    int off = g_off[n];
    int deg = g_deg[n];
    float4 hd = *(const float4*)&g_h[(size_t)n * DD + lane * 4];

    float4 aP = make_float4(0.f,0.f,0.f,0.f), q0 = aP, q1 = aP, q2 = aP;
    float za = 0.f, z0 = 0.f, z1 = 0.f, z2 = 0.f;

    int j = 0;
    while (j < deg) {
        int cnt = min(deg - j, 32);
        long long my = 0;
        if (lane < cnt) {
            int2 se = __ldg(&g_epack[off + j + lane]);
            my = ((long long)se.y << 32) | (unsigned int)se.x;
        }
        int jj = 0;
        int u4 = cnt & ~3;
        for (; jj < u4; jj += 4) {
            float4 hs[4], eg[4]; float p[4];
            #pragma unroll
            for (int u = 0; u < 4; u++) {
                long long pk = __shfl_sync(0xffffffffu, my, jj + u);
                int s = (int)(unsigned int)pk;
                int e = (int)(pk >> 32);
                hs[u] = *(const float4*)&g_h[(size_t)s * DD + lane * 4];
                eg[u] = *(const float4*)&g_eg4f[(size_t)e * 4];
                p[u] = hs[u].x*hd.x + hs[u].y*hd.y + hs[u].z*hd.z + hs[u].w*hd.w;
            }
            #pragma unroll
            for (int o = 16; o; o >>= 1) {
                #pragma unroll
                for (int u = 0; u < 4; u++) p[u] += __shfl_xor_sync(0xffffffffu, p[u], o);
            }
            #pragma unroll
            for (int u = 0; u < 4; u++) {
                float ea = __expf(p[u]);
                za += ea; z0 += eg[u].x; z1 += eg[u].y; z2 += eg[u].z;
                aP.x += ea*hs[u].x; aP.y += ea*hs[u].y; aP.z += ea*hs[u].z; aP.w += ea*hs[u].w;
                q0.x += eg[u].x*hs[u].x; q0.y += eg[u].x*hs[u].y; q0.z += eg[u].x*hs[u].z; q0.w += eg[u].x*hs[u].w;
                q1.x += eg[u].y*hs[u].x; q1.y += eg[u].y*hs[u].y; q1.z += eg[u].y*hs[u].z; q1.w += eg[u].y*hs[u].w;
                q2.x += eg[u].z*hs[u].x; q2.y += eg[u].z*hs[u].y; q2.z += eg[u].z*hs[u].z; q2.w += eg[u].z*hs[u].w;
            }
        }
        for (; jj < cnt; jj++) {
            long long pk = __shfl_sync(0xffffffffu, my, jj);
            int s = (int)(unsigned int)pk;
            int e = (int)(pk >> 32);
            float4 hs = *(const float4*)&g_h[(size_t)s * DD + lane * 4];
            float4 eg = *(const float4*)&g_eg4f[(size_t)e * 4];
            float pa = hs.x*hd.x + hs.y*hd.y + hs.z*hd.z + hs.w*hd.w;
            #pragma unroll
            for (int o = 16; o; o >>= 1) pa += __shfl_xor_sync(0xffffffffu, pa, o);
            float ea = __expf(pa);
            za += ea; z0 += eg.x; z1 += eg.y; z2 += eg.z;
            aP.x += ea*hs.x; aP.y += ea*hs.y; aP.z += ea*hs.z; aP.w += ea*hs.w;
            q0.x += eg.x*hs.x; q0.y += eg.x*hs.y; q0.z += eg.x*hs.z; q0.w += eg.x*hs.w;
            q1.x += eg.y*hs.x; q1.y += eg.y*hs.y; q1.z += eg.y*hs.z; q1.w += eg.y*hs.w;
            q2.x += eg.z*hs.x; q2.y += eg.z*hs.y; q2.z += eg.z*hs.z; q2.w += eg.z*hs.w;
        }
        j += cnt;
    }

    float sP = 0.f, s0 = 0.f, s1 = 0.f, s2 = 0.f;
    if (deg > 0) {
        sP = 1.f / (3.f * za); s0 = 1.f / (3.f * z0);
        s1 = 1.f / (3.f * z1); s2 = 1.f / (3.f * z2);
    }
    float* base = g_acc + (size_t)n * 512;
    *(float4*)(base + lane * 4)       = make_float4(aP.x*sP, aP.y*sP, aP.z*sP, aP.w*sP);
    *(float4*)(base + 128 + lane * 4) = make_float4(q0.x*s0, q0.y*s0, q0.z*s0, q0.w*s0);
    *(float4*)(base + 256 + lane * 4) = make_float4(q1.x*s1, q1.y*s1, q1.z*s1, q1.w*s1);
    *(float4*)(base + 384 + lane * 4) = make_float4(q2.x*s2, q2.y*s2, q2.z*s2, q2.w*s2);
    if (lane == 0) g_za[n] = (deg > 0) ? za : 0.f;
}

// ---------------- kernel D: finalize per node (tf32 mma, weights hi/lo) ----------------
#define FW_STRIDE 132
#define SMEM_FIN  ((16896 + 8448) * 4)

__global__ void __launch_bounds__(256, 2) k_final(const float* __restrict__ nf,
                                                  const float* __restrict__ outb,
                                                  const float* __restrict__ gW,
                                                  const float* __restrict__ gb,
                                                  float* __restrict__ out)
{
    extern __shared__ float sm[];
    float* WsT = sm;
    float* As  = sm + 16896;

    int tid = threadIdx.x;
    int w = tid >> 5, lane = tid & 31;
    int g = lane >> 2, tig = lane & 3;
    int nbase = blockIdx.x * NB;

    float c[8][4];
    #pragma unroll
    for (int i = 0; i < 8; i++) { c[i][0]=0.f; c[i][1]=0.f; c[i][2]=0.f; c[i][3]=0.f; }

    for (int ph = 0; ph < 4; ph++) {
        __syncthreads();
        for (int q = tid; q < 2048; q += 256) {
            int nn = q >> 5, kq = q & 31;
            int gn = nbase + nn;
            float4 v = make_float4(0.f,0.f,0.f,0.f);
            if (gn < NN) v = *(const float4*)&g_acc[(size_t)gn * 512 + ph * 128 + kq * 4];
            v.x = tf32f(v.x); v.y = tf32f(v.y); v.z = tf32f(v.z); v.w = tf32f(v.w);
            *(float4*)&As[nn * FW_STRIDE + kq * 4] = v;
        }
        #pragma unroll
        for (int pass = 0; pass < 2; pass++) {
            __syncthreads();
            const float* Csrc = (pass ? g_Ct_lo : g_Ct_hi) + ph * 16384;
            for (int q = tid; q < 4096; q += 256) {
                int rr = q >> 5, kq = q & 31;
                *(float4*)&WsT[rr * FW_STRIDE + kq * 4] = *(const float4*)&Csrc[rr * 128 + kq * 4];
            }
            __syncthreads();
            uint32_t a0[16], a1[16], a2[16], a3[16];
            const float* w0 = &WsT[(w * 16 + g) * FW_STRIDE];
            const float* w1 = &WsT[(w * 16 + 8 + g) * FW_STRIDE];
            #pragma unroll
            for (int kk = 0; kk < 16; kk++) {
                a0[kk] = __float_as_uint(w0[kk * 8 + tig]);
                a2[kk] = __float_as_uint(w0[kk * 8 + tig + 4]);
                a1[kk] = __float_as_uint(w1[kk * 8 + tig]);
                a3[kk] = __float_as_uint(w1[kk * 8 + tig + 4]);
            }
            #pragma unroll
            for (int nt = 0; nt < 8; nt++) {
                const float* bp = &As[(nt * 8 + g) * FW_STRIDE];
                #pragma unroll
                for (int kk = 0; kk < 16; kk++) {
                    uint32_t b0 = __float_as_uint(bp[kk * 8 + tig]);
                    uint32_t b1 = __float_as_uint(bp[kk * 8 + tig + 4]);
                    mma_tf32(c[nt][0], c[nt][1], c[nt][2], c[nt][3],
                             a0[kk], a1[kk], a2[kk], a3[kk], b0, b1);
                }
            }
        }
    }

    __syncthreads();
    #pragma unroll
    for (int nt = 0; nt < 8; nt++) {
        int n0 = nt * 8 + tig * 2;
        As[n0 * FW_STRIDE + w * 16 + g]           = c[nt][0];
        As[(n0 + 1) * FW_STRIDE + w * 16 + g]     = c[nt][1];
        As[n0 * FW_STRIDE + w * 16 + 8 + g]       = c[nt][2];
        As[(n0 + 1) * FW_STRIDE + w * 16 + 8 + g] = c[nt][3];
    }
    __syncthreads();

    float4 b4  = *(const float4*)&outb[lane * 4];
    float4 gw4 = *(const float4*)&gW[lane * 4];
    float gb0 = __ldg(gb);
    #pragma unroll
    for (int t = 0; t < 8; t++) {
        int i = w * 8 + t;
        int n = nbase + i;
        if (n >= NN) break;
        float4 vv = *(const float4*)&As[i * FW_STRIDE + lane * 4];
        bool ok = (g_za[n] > 0.f);
        float4 pre = make_float4(fmaxf(vv.x + b4.x, 0.f), fmaxf(vv.y + b4.y, 0.f),
                                 fmaxf(vv.z + b4.z, 0.f), fmaxf(vv.w + b4.w, 0.f));
        float4 hv  = *(const float4*)&g_h[(size_t)n * DD + lane * 4];
        float4 ho  = ok ? pre : hv;
        float4 nfv = *(const float4*)&nf[(size_t)n * DD + lane * 4];
        float gp = nfv.x * gw4.x + nfv.y * gw4.y + nfv.z * gw4.z + nfv.w * gw4.w;
        #pragma unroll
        for (int o = 16; o; o >>= 1) gp += __shfl_xor_sync(0xffffffffu, gp, o);
        float gate = sigmoidf_(gp + gb0);
        float4 oo = make_float4(gate * ho.x + (1.f - gate) * nfv.x,
                                gate * ho.y + (1.f - gate) * nfv.y,
                                gate * ho.z + (1.f - gate) * nfv.z,
                                gate * ho.w + (1.f - gate) * nfv.w);
        *(float4*)&out[(size_t)n * DD + lane * 4] = oo;
    }
}

// ---------------- launcher ----------------
extern "C" void kernel_launch(void* const* d_in, const int* in_sizes, int n_in,
                              void* d_out, int out_size)
{
    const float* nf   = (const float*)d_in[0];
    const float* ef   = (const float*)d_in[1];
    const int*   src  = (const int*)  d_in[2];
    const int*   dst  = (const int*)  d_in[3];
    const float* natt = (const float*)d_in[4];
    const float* relW = (const float*)d_in[5];
    const float* W1   = (const float*)d_in[6];
    const float* b1   = (const float*)d_in[7];
    const float* W2   = (const float*)d_in[8];
    const float* b2   = (const float*)d_in[9];
    const float* nfcW = (const float*)d_in[10];
    const float* nfcb = (const float*)d_in[11];
    const float* efcW = (const float*)d_in[12];
    const float* efcb = (const float*)d_in[13];
    const float* outW = (const float*)d_in[14];
    const float* outb = (const float*)d_in[15];
    const float* gW   = (const float*)d_in[16];
    const float* gb   = (const float*)d_in[17];
    float* out = (float*)d_out;

    static cudaStream_t s_side = nullptr;
    static cudaEvent_t e_fork = nullptr, e_fill = nullptr, e_comb = nullptr;
    if (s_side == nullptr) {
        cudaStreamCreateWithFlags(&s_side, cudaStreamNonBlocking);
        cudaEventCreateWithFlags(&e_fork, cudaEventDisableTiming);
        cudaEventCreateWithFlags(&e_fill, cudaEventDisableTiming);
        cudaEventCreateWithFlags(&e_comb, cudaEventDisableTiming);
    }

    void* pDeg;
    cudaGetSymbolAddress(&pDeg, g_deg);

    cudaFuncSetAttribute(k_node_fc, cudaFuncAttributeMaxDynamicSharedMemorySize, SMEM_NFC);
    cudaFuncSetAttribute(k_mlp,     cudaFuncAttributeMaxDynamicSharedMemorySize, SMEM_MLP);
    cudaFuncSetAttribute(k_final,   cudaFuncAttributeMaxDynamicSharedMemorySize, SMEM_FIN);

    // fork: CSR build + combine on side stream (independent of main compute chain)
    cudaEventRecord(e_fork, 0);
    cudaStreamWaitEvent(s_side, e_fork, 0);
    cudaMemsetAsync(pDeg, 0, NN * sizeof(int), s_side);
    k_hist<<<(EE + 255) / 256, 256, 0, s_side>>>(dst);
    k_scan<<<1, 1024, 0, s_side>>>();
    k_fill<<<(EE + 255) / 256, 256, 0, s_side>>>(src, dst);
    cudaEventRecord(e_fill, s_side);
    k_combine<<<512, 128, 0, s_side>>>(natt, relW, outW);
    cudaEventRecord(e_comb, s_side);

    // main chain
    k_prep_early<<<320, 128>>>(nfcW, efcW, efcb, W1, b1);
    k_node_fc<<<(NN + 127) / 128, 256, SMEM_NFC>>>(nf, nfcb);
    k_mlp<<<GRID_MLP, 768, SMEM_MLP>>>(ef, W2, b2);

    // join: gather needs CSR; final needs combine
    cudaStreamWaitEvent(0, e_fill, 0);
    k_gather<<<(NN + 7) / 8, 256>>>();
    cudaStreamWaitEvent(0, e_comb, 0);
    k_final<<<(NN + NB - 1) / NB, 256, SMEM_FIN>>>(nf, outb, gW, gb, out);
}